// round 12
// baseline (speedup 1.0000x reference)
#include <cuda_runtime.h>
#include <cuda_bf16.h>
#include <cstdint>
#include <cstddef>

#define NTOK 65536  // 16 * 64 * 64 tokens

// ---------------- scratch (no allocations allowed) ----------------
__device__ __nv_bfloat16 g_xn_h [(size_t)NTOK * 256];
__device__ __nv_bfloat16 g_xn_l [(size_t)NTOK * 256];
__device__ float         g_qkv  [(size_t)NTOK * 768];
__device__ __nv_bfloat16 g_at_h [(size_t)NTOK * 256];
__device__ __nv_bfloat16 g_at_l [(size_t)NTOK * 256];
__device__ float         g_attn2[(size_t)NTOK * 256];
__device__ float         g_y    [(size_t)NTOK * 256];
__device__ __nv_bfloat16 g_z_h  [(size_t)NTOK * 256];
__device__ __nv_bfloat16 g_z_l  [(size_t)NTOK * 256];
__device__ __nv_bfloat16 g_h1_h [(size_t)NTOK * 1024];
__device__ __nv_bfloat16 g_h1_l [(size_t)NTOK * 1024];
__device__ float         g_mlp  [(size_t)NTOK * 256];
// packed bf16 hi/lo weights: in_w(196608) comb_w(65536) fc1_w(262144) fc2_w(262144)
__device__ __nv_bfloat16 g_w_h[786432];
__device__ __nv_bfloat16 g_w_l[786432];
__device__ float         g_bcomb[256];

#define OFF_INW  0
#define OFF_CMBW 196608
#define OFF_FC1W 262144
#define OFF_FC2W 524288

// ---------------- small helpers ----------------
__device__ __forceinline__ void split2(float v, __nv_bfloat16& h, __nv_bfloat16& l) {
    h = __float2bfloat16(v);
    l = __float2bfloat16(v - __bfloat162float(h));
}

__device__ __forceinline__ uint32_t smem_u32(const void* p) {
    uint32_t a;
    asm("{ .reg .u64 t; cvta.to.shared.u64 t, %1; cvt.u32.u64 %0, t; }" : "=r"(a) : "l"(p));
    return a;
}

// packed f32x2 fma (Blackwell): d = a*b + d, lanewise on two fp32
__device__ __forceinline__ void fma2(unsigned long long& d, unsigned long long a,
                                     unsigned long long b) {
    asm("fma.rn.f32x2 %0, %1, %2, %0;" : "+l"(d) : "l"(a), "l"(b));
}
__device__ __forceinline__ float upk_sum(unsigned long long v) {
    float lo, hi;
    asm("mov.b64 {%0,%1}, %2;" : "=f"(lo), "=f"(hi) : "l"(v));
    return lo + hi;
}

#define CPA16(dst, src) \
    asm volatile("cp.async.cg.shared.global [%0], [%1], 16;\n" :: "r"(dst), "l"(src))
#define CPA_COMMIT() asm volatile("cp.async.commit_group;\n" ::: "memory")
#define CPA_WAIT1()  asm volatile("cp.async.wait_group 1;\n" ::: "memory")
#define CPA_WAIT0()  asm volatile("cp.async.wait_group 0;\n" ::: "memory")

__device__ __forceinline__ void ldsm4(uint32_t* r, uint32_t addr) {
    asm volatile("ldmatrix.sync.aligned.m8n8.x4.shared.b16 {%0,%1,%2,%3}, [%4];\n"
                 : "=r"(r[0]), "=r"(r[1]), "=r"(r[2]), "=r"(r[3]) : "r"(addr));
}
__device__ __forceinline__ void mma16816(float* c, const uint32_t* a, uint32_t b0, uint32_t b1) {
    asm volatile(
        "mma.sync.aligned.m16n8k16.row.col.f32.bf16.bf16.f32 "
        "{%0,%1,%2,%3}, {%4,%5,%6,%7}, {%8,%9}, {%0,%1,%2,%3};\n"
        : "+f"(c[0]), "+f"(c[1]), "+f"(c[2]), "+f"(c[3])
        : "r"(a[0]), "r"(a[1]), "r"(a[2]), "r"(a[3]), "r"(b0), "r"(b1));
}

// ---------------- mma.sync split-bf16 GEMM ----------------
// C[M,N] = A[M,K] @ B[N,K]^T + bias, A/B as (hi,lo) bf16 pairs; 3-pass split.
// Block 128x128, 8 warps (2x4), warp tile 64x32, BK=32, cp.async double buffer.
// smem tile: 128 rows x 80B -> ldmatrix conflict-free. 80KB smem, forced 2 CTA/SM.
// Al reloads staggered into pass1 so pass2 never sees raw ldsm latency.
#define ROW_B       80
#define TILE_B      (128 * ROW_B)     // 10240
#define STAGE_B     (4 * TILE_B)      // Ah | Al | Bh | Bl = 40960
#define GEMM_SMEM   (2 * STAGE_B)     // 81920

template <int OUTMODE /*0=f32, 1=hilo*/, bool GELU>
__global__ __launch_bounds__(256, 2)
void mma_gemm(const __nv_bfloat16* __restrict__ Ah, const __nv_bfloat16* __restrict__ Al,
              const __nv_bfloat16* __restrict__ Bh, const __nv_bfloat16* __restrict__ Bl,
              const float* __restrict__ bias,
              float* __restrict__ Cf,
              __nv_bfloat16* __restrict__ Ch, __nv_bfloat16* __restrict__ Cl,
              int N, int K) {
    extern __shared__ char smem[];
    const uint32_t sb0 = smem_u32(smem);
    const int tid = threadIdx.x, lane = tid & 31, wid = tid >> 5;
    const int wm = wid >> 2, wn = wid & 3;        // 2 x 4 warp grid
    const int bm = blockIdx.y * 128, bn = blockIdx.x * 128;

    float acc[4][4][4];
#pragma unroll
    for (int i = 0; i < 4; i++)
#pragma unroll
        for (int j = 0; j < 4; j++)
#pragma unroll
            for (int k = 0; k < 4; k++) acc[i][j][k] = 0.f;

    const int nc = K >> 5;  // BK=32 chunks

    auto load_stage = [&](int c, int s) {
        const uint32_t base = sb0 + s * STAGE_B;
        const size_t k0 = (size_t)c << 5;
#pragma unroll
        for (int it = 0; it < 2; ++it) {
            int e = it * 256 + tid;
            int row = e >> 2, ch = e & 3;
            uint32_t d = base + row * ROW_B + ch * 16;
            size_t ga = ((size_t)(bm + row) * K + k0 + ch * 8) * 2;
            size_t gb = ((size_t)(bn + row) * K + k0 + ch * 8) * 2;
            CPA16(d,              (const char*)Ah + ga);
            CPA16(d + TILE_B,     (const char*)Al + ga);
            CPA16(d + 2 * TILE_B, (const char*)Bh + gb);
            CPA16(d + 3 * TILE_B, (const char*)Bl + gb);
        }
        CPA_COMMIT();
    };

    load_stage(0, 0);

    // per-warp ldmatrix base offsets (within a tile)
    const uint32_t a_off = (uint32_t)((wm * 64 + (lane & 15)) * ROW_B + (lane >> 4) * 16);
    const uint32_t b_off = (uint32_t)((wn * 32 + (lane & 7) + ((lane >> 4) << 3)) * ROW_B +
                                      ((lane >> 3) & 1) * 16);

    for (int c = 0; c < nc; ++c) {
        const int s = c & 1;
        if (c + 1 < nc) { load_stage(c + 1, (c + 1) & 1); CPA_WAIT1(); }
        else            { CPA_WAIT0(); }
        __syncthreads();

        const uint32_t base = sb0 + s * STAGE_B;
        const uint32_t ab = base + a_off;
        const uint32_t bb = base + 2 * TILE_B + b_off;
#pragma unroll
        for (int ks = 0; ks < 2; ++ks) {
            uint32_t a[4][4], bh[2][4], bl[2][4];
#pragma unroll
            for (int mf = 0; mf < 4; ++mf) ldsm4(a[mf], ab + mf * 16 * ROW_B + ks * 32);
#pragma unroll
            for (int nf = 0; nf < 2; ++nf) ldsm4(bh[nf], bb + nf * 16 * ROW_B + ks * 32);
#pragma unroll
            for (int nf = 0; nf < 2; ++nf) ldsm4(bl[nf], bb + TILE_B + nf * 16 * ROW_B + ks * 32);
            // pass 0: Ah * Bh
#pragma unroll
            for (int mf = 0; mf < 4; ++mf)
#pragma unroll
                for (int nf = 0; nf < 2; ++nf)
#pragma unroll
                    for (int sub = 0; sub < 2; ++sub)
                        mma16816(acc[mf][nf * 2 + sub], a[mf],
                                 bh[nf][sub * 2], bh[nf][sub * 2 + 1]);
            // pass 1: Ah * Bl ; stagger reload a[mf] <- Al right after last use
#pragma unroll
            for (int mf = 0; mf < 4; ++mf) {
#pragma unroll
                for (int nf = 0; nf < 2; ++nf)
#pragma unroll
                    for (int sub = 0; sub < 2; ++sub)
                        mma16816(acc[mf][nf * 2 + sub], a[mf],
                                 bl[nf][sub * 2], bl[nf][sub * 2 + 1]);
                ldsm4(a[mf], ab + TILE_B + mf * 16 * ROW_B + ks * 32);
            }
            // pass 2: Al * Bh
#pragma unroll
            for (int mf = 0; mf < 4; ++mf)
#pragma unroll
                for (int nf = 0; nf < 2; ++nf)
#pragma unroll
                    for (int sub = 0; sub < 2; ++sub)
                        mma16816(acc[mf][nf * 2 + sub], a[mf],
                                 bh[nf][sub * 2], bh[nf][sub * 2 + 1]);
        }
        __syncthreads();
    }

    // epilogue straight from fragments
#pragma unroll
    for (int mf = 0; mf < 4; ++mf) {
#pragma unroll
        for (int nf8 = 0; nf8 < 4; ++nf8) {
            int row = bm + wm * 64 + mf * 16 + (lane >> 2);
            int col = bn + wn * 32 + nf8 * 8 + (lane & 3) * 2;
            float b0 = bias[col], b1 = bias[col + 1];
#pragma unroll
            for (int half = 0; half < 2; ++half) {
                int r = row + half * 8;
                float v0 = acc[mf][nf8][half * 2 + 0] + b0;
                float v1 = acc[mf][nf8][half * 2 + 1] + b1;
                if (GELU) { v0 = v0 * normcdff(v0); v1 = v1 * normcdff(v1); }
                size_t o = (size_t)r * N + col;
                if (OUTMODE == 0) {
                    *(float2*)(Cf + o) = make_float2(v0, v1);
                } else {
                    __nv_bfloat16 h0, l0, h1, l1;
                    split2(v0, h0, l0); split2(v1, h1, l1);
                    *(__nv_bfloat162*)(Ch + o) = __nv_bfloat162(h0, h1);
                    *(__nv_bfloat162*)(Cl + o) = __nv_bfloat162(l0, l1);
                }
            }
        }
    }
}

// ---------------- weight fp32 -> (hi,lo) bf16, 3 segments in one launch ----
__global__ void cvtw3(const float* __restrict__ in_w, const float* __restrict__ fc1_w,
                      const float* __restrict__ fc2_w,
                      __nv_bfloat16* __restrict__ wh, __nv_bfloat16* __restrict__ wl) {
    int i = blockIdx.x * 256 + threadIdx.x;  // 0 .. 720895
    const float* src; int dst;
    if (i < 196608)      { src = in_w;  dst = OFF_INW  + i; }
    else if (i < 458752) { src = fc1_w - 196608; dst = OFF_FC1W + (i - 196608); }
    else                 { src = fc2_w - 458752; dst = OFF_FC2W + (i - 458752); }
    __nv_bfloat16 hh, ll;
    split2(src[i], hh, ll);
    wh[dst] = hh; wl[dst] = ll;
}

// ---------------- combined out∘proj weight: W = proj_w @ out_w ----------------
__global__ void wcomb(const float* __restrict__ proj_w, const float* __restrict__ out_w,
                      const float* __restrict__ out_b, const float* __restrict__ proj_b,
                      __nv_bfloat16* __restrict__ wh, __nv_bfloat16* __restrict__ wl,
                      float* __restrict__ bcomb) {
    int i = blockIdx.x;       // output row
    int j = threadIdx.x;      // output col (coalesced over out_w)
    float s = 0.f;
    for (int k = 0; k < 256; ++k)
        s += proj_w[i * 256 + k] * out_w[k * 256 + j];
    __nv_bfloat16 hh, ll; split2(s, hh, ll);
    wh[OFF_CMBW + i * 256 + j] = hh;
    wl[OFF_CMBW + i * 256 + j] = ll;
    if (j == 0) {
        float b = proj_b[i];
        for (int k = 0; k < 256; ++k) b += proj_w[i * 256 + k] * out_b[k];
        bcomb[i] = b;
    }
}

// (b,h,w) -> token index T in shifted-window order
__device__ __forceinline__ int src_to_token(int b, int h, int w) {
    int hs = (h + 60) & 63, ws = (w + 60) & 63;
    return ((b * 8 + (hs >> 3)) * 8 + (ws >> 3)) * 64 + (hs & 7) * 8 + (ws & 7);
}

// ---------------- LN1 + shift + window partition -> bf16 hi/lo ----------------
#define LN_SMEM (256 * 65 * 4)
__global__ __launch_bounds__(256)
void ln1_part(const float* __restrict__ x,
              const float* __restrict__ g, const float* __restrict__ bb,
              __nv_bfloat16* __restrict__ oh, __nv_bfloat16* __restrict__ ol) {
    extern __shared__ float xs[];  // [256][65]
    int b = blockIdx.x >> 6, h = blockIdx.x & 63;
    int tid = threadIdx.x;
    const float* xp = x + (size_t)b * 1048576 + h * 64;
#pragma unroll
    for (int it = 0; it < 64; ++it) {
        int e = it * 256 + tid;
        int c = e >> 6, w = e & 63;
        xs[c * 65 + w] = xp[(size_t)c * 4096 + w];
    }
    __syncthreads();
    int warp = tid >> 5, lane = tid & 31;
#pragma unroll 1
    for (int t = 0; t < 8; ++t) {
        int w = t * 8 + warp;
        float v[8]; float s = 0.f;
#pragma unroll
        for (int k = 0; k < 8; k++) { v[k] = xs[(k * 32 + lane) * 65 + w]; s += v[k]; }
#pragma unroll
        for (int o = 16; o; o >>= 1) s += __shfl_xor_sync(0xffffffffu, s, o);
        float mu = s * 0.00390625f;
        float q = 0.f;
#pragma unroll
        for (int k = 0; k < 8; k++) { float d = v[k] - mu; q += d * d; }
#pragma unroll
        for (int o = 16; o; o >>= 1) q += __shfl_xor_sync(0xffffffffu, q, o);
        float rs = rsqrtf(q * 0.00390625f + 1e-6f);
        size_t tb = (size_t)src_to_token(b, h, w) * 256;
#pragma unroll
        for (int k = 0; k < 8; k++) {
            int c = k * 32 + lane;
            float val = (v[k] - mu) * rs * g[c] + bb[c];
            __nv_bfloat16 hh, ll; split2(val, hh, ll);
            oh[tb + c] = hh; ol[tb + c] = ll;
        }
    }
}

// ---------------- attention: one block per (window, head) ----------------
// f32x2-packed: QK^T packs d-pairs, SV packs j-pairs (reduction-dim packing ->
// both operands are contiguous float2 smem loads, no shuffle/pack overhead).
__global__ __launch_bounds__(256)
void attn_kernel(const float* __restrict__ qkv,
                 __nv_bfloat16* __restrict__ oh, __nv_bfloat16* __restrict__ ol) {
    __shared__ __align__(16) float Qs[64][34];   // [row][d], stride 34 (8B-aligned pairs)
    __shared__ __align__(16) float Ks[64][34];
    __shared__ __align__(16) float Vt[32][66];   // transposed: [d][row]
    __shared__ __align__(16) float S[64][66];
    __shared__ float rinv[64];
    int win = blockIdx.x, head = blockIdx.y;
    int tid = threadIdx.x;
    size_t base = (size_t)win * 64 * 768 + head * 32;

    // load q/k/v: 64 rows x 8 float4 each; V transposed into Vt
#pragma unroll
    for (int e = tid; e < 512; e += 256) {
        int i = e >> 3, f4 = e & 7, d = f4 * 4;
        const float* rp = qkv + base + (size_t)i * 768;
        float4 q = *((const float4*)rp + f4);
        float4 k = *((const float4*)(rp + 256) + f4);
        float4 v = *((const float4*)(rp + 512) + f4);
        Qs[i][d] = q.x; Qs[i][d+1] = q.y; Qs[i][d+2] = q.z; Qs[i][d+3] = q.w;
        Ks[i][d] = k.x; Ks[i][d+1] = k.y; Ks[i][d+2] = k.z; Ks[i][d+3] = k.w;
        Vt[d+0][i] = v.x; Vt[d+1][i] = v.y; Vt[d+2][i] = v.z; Vt[d+3][i] = v.w;
    }
    __syncthreads();

    // QK^T: thread (ty,tx) covers rows {ty+16r}, cols {tx+16c}; packed over d
    {
        int ty = tid >> 4, tx = tid & 15;
        unsigned long long s2[4][4];
#pragma unroll
        for (int r = 0; r < 4; ++r)
#pragma unroll
            for (int c2 = 0; c2 < 4; ++c2) s2[r][c2] = 0ULL;
#pragma unroll
        for (int d2 = 0; d2 < 16; ++d2) {
            unsigned long long q2[4], k2[4];
#pragma unroll
            for (int r = 0; r < 4; ++r)
                q2[r] = *(const unsigned long long*)&Qs[ty + 16 * r][2 * d2];
#pragma unroll
            for (int c2 = 0; c2 < 4; ++c2)
                k2[c2] = *(const unsigned long long*)&Ks[tx + 16 * c2][2 * d2];
#pragma unroll
            for (int r = 0; r < 4; ++r)
#pragma unroll
                for (int c2 = 0; c2 < 4; ++c2) fma2(s2[r][c2], q2[r], k2[c2]);
        }
        const float scale = 0.17677669529663687f;  // 1/sqrt(32)
#pragma unroll
        for (int r = 0; r < 4; ++r)
#pragma unroll
            for (int c2 = 0; c2 < 4; ++c2)
                S[ty + 16 * r][tx + 16 * c2] = upk_sum(s2[r][c2]) * scale;
    }
    __syncthreads();

    // softmax: 4 lanes per row, 16 cols each
    {
        int row = tid >> 2, j0 = (tid & 3) * 16;
        float m = -1e30f;
#pragma unroll
        for (int k = 0; k < 16; ++k) m = fmaxf(m, S[row][j0 + k]);
        m = fmaxf(m, __shfl_xor_sync(0xffffffffu, m, 1));
        m = fmaxf(m, __shfl_xor_sync(0xffffffffu, m, 2));
        float sum = 0.f;
#pragma unroll
        for (int k = 0; k < 16; ++k) {
            float e = __expf(S[row][j0 + k] - m);
            S[row][j0 + k] = e; sum += e;
        }
        sum += __shfl_xor_sync(0xffffffffu, sum, 1);
        sum += __shfl_xor_sync(0xffffffffu, sum, 2);
        if ((tid & 3) == 0) rinv[row] = 1.f / sum;
    }
    __syncthreads();

    // SV: thread covers rows {g, g+32}, 4 cols; packed over j
    {
        int g = tid >> 3, dc = (tid & 7) * 4;
        unsigned long long a2[2][4];
#pragma unroll
        for (int r = 0; r < 2; ++r)
#pragma unroll
            for (int c2 = 0; c2 < 4; ++c2) a2[r][c2] = 0ULL;
#pragma unroll
        for (int j2 = 0; j2 < 32; ++j2) {
            unsigned long long s0 = *(const unsigned long long*)&S[g][2 * j2];
            unsigned long long s1 = *(const unsigned long long*)&S[g + 32][2 * j2];
#pragma unroll
            for (int c2 = 0; c2 < 4; ++c2) {
                unsigned long long v2 = *(const unsigned long long*)&Vt[dc + c2][2 * j2];
                fma2(a2[0][c2], s0, v2);
                fma2(a2[1][c2], s1, v2);
            }
        }
        float ri0 = rinv[g], ri1 = rinv[g + 32];
        size_t o0 = (size_t)(win * 64 + g) * 256 + head * 32 + dc;
        size_t o1 = o0 + (size_t)32 * 256;
#pragma unroll
        for (int c2 = 0; c2 < 4; ++c2) {
            __nv_bfloat16 hh, ll;
            split2(upk_sum(a2[0][c2]) * ri0, hh, ll);
            oh[o0 + c2] = hh; ol[o0 + c2] = ll;
            split2(upk_sum(a2[1][c2]) * ri1, hh, ll);
            oh[o1 + c2] = hh; ol[o1 + c2] = ll;
        }
    }
}

// ---------------- window reverse + residual + LN2 ----------------
__global__ __launch_bounds__(256)
void resid_ln2(const float* __restrict__ x, const float* __restrict__ a,
               const float* __restrict__ g, const float* __restrict__ bb,
               float* __restrict__ yout,
               __nv_bfloat16* __restrict__ zh, __nv_bfloat16* __restrict__ zl) {
    extern __shared__ float xs[];  // [256][65]
    int b = blockIdx.x >> 6, h = blockIdx.x & 63;
    int tid = threadIdx.x;
    const float* xp = x + (size_t)b * 1048576 + h * 64;
#pragma unroll
    for (int it = 0; it < 64; ++it) {
        int e = it * 256 + tid;
        int c = e >> 6, w = e & 63;
        xs[c * 65 + w] = xp[(size_t)c * 4096 + w];
    }
    __syncthreads();
    int warp = tid >> 5, lane = tid & 31;
#pragma unroll 1
    for (int t = 0; t < 8; ++t) {
        int w = t * 8 + warp;
        size_t tb = (size_t)src_to_token(b, h, w) * 256;
        float v[8]; float s = 0.f;
#pragma unroll
        for (int k = 0; k < 8; k++) {
            int c = k * 32 + lane;
            v[k] = xs[c * 65 + w] + a[tb + c];
            s += v[k];
        }
#pragma unroll
        for (int o = 16; o; o >>= 1) s += __shfl_xor_sync(0xffffffffu, s, o);
        float mu = s * 0.00390625f;
        float q = 0.f;
#pragma unroll
        for (int k = 0; k < 8; k++) { float d = v[k] - mu; q += d * d; }
#pragma unroll
        for (int o = 16; o; o >>= 1) q += __shfl_xor_sync(0xffffffffu, q, o);
        float rs = rsqrtf(q * 0.00390625f + 1e-6f);
#pragma unroll
        for (int k = 0; k < 8; k++) {
            int c = k * 32 + lane;
            yout[tb + c] = v[k];
            float val = (v[k] - mu) * rs * g[c] + bb[c];
            __nv_bfloat16 hh, ll; split2(val, hh, ll);
            zh[tb + c] = hh; zl[tb + c] = ll;
        }
    }
}

// ---------------- final: out[b,c,h,w] = y_tok + mlp_tok, smem transpose ----
#define FIN_SMEM (64 * 257 * 4)
__global__ __launch_bounds__(256)
void final_add(const float* __restrict__ y, const float* __restrict__ m,
               float* __restrict__ out) {
    extern __shared__ float ss[];  // [64 tokens][257]
    int b = blockIdx.x >> 6, h = blockIdx.x & 63;
    int tid = threadIdx.x;
    int warp = tid >> 5, lane = tid & 31;
#pragma unroll 1
    for (int t = 0; t < 8; ++t) {
        int w = t * 8 + warp;
        size_t tb = (size_t)src_to_token(b, h, w) * 256;
#pragma unroll
        for (int k = 0; k < 8; k++) {
            int c = k * 32 + lane;
            ss[w * 257 + c] = y[tb + c] + m[tb + c];
        }
    }
    __syncthreads();
    float* op = out + (size_t)b * 1048576 + h * 64;
#pragma unroll
    for (int it = 0; it < 64; ++it) {
        int e = it * 256 + tid;
        int c = e >> 6, w = e & 63;
        op[(size_t)c * 4096 + w] = ss[w * 257 + c];
    }
}

// ---------------- launch ----------------
extern "C" void kernel_launch(void* const* d_in, const int* in_sizes, int n_in,
                              void* d_out, int out_size) {
    const float* x      = (const float*)d_in[0];
    const float* n1g    = (const float*)d_in[1];
    const float* n1b    = (const float*)d_in[2];
    const float* in_w   = (const float*)d_in[3];
    const float* in_b   = (const float*)d_in[4];
    const float* out_w  = (const float*)d_in[5];
    const float* out_b  = (const float*)d_in[6];
    const float* proj_w = (const float*)d_in[7];
    const float* proj_b = (const float*)d_in[8];
    const float* n2g    = (const float*)d_in[9];
    const float* n2b    = (const float*)d_in[10];
    const float* fc1_w  = (const float*)d_in[11];
    const float* fc1_b  = (const float*)d_in[12];
    const float* fc2_w  = (const float*)d_in[13];
    const float* fc2_b  = (const float*)d_in[14];
    float* out = (float*)d_out;

    __nv_bfloat16 *xnh, *xnl, *ath, *atl, *zh, *zl, *h1h, *h1l, *wh, *wl;
    float *qkv, *attn2, *yb, *mlp, *bcomb;
    cudaGetSymbolAddress((void**)&xnh,   g_xn_h);
    cudaGetSymbolAddress((void**)&xnl,   g_xn_l);
    cudaGetSymbolAddress((void**)&qkv,   g_qkv);
    cudaGetSymbolAddress((void**)&ath,   g_at_h);
    cudaGetSymbolAddress((void**)&atl,   g_at_l);
    cudaGetSymbolAddress((void**)&attn2, g_attn2);
    cudaGetSymbolAddress((void**)&yb,    g_y);
    cudaGetSymbolAddress((void**)&zh,    g_z_h);
    cudaGetSymbolAddress((void**)&zl,    g_z_l);
    cudaGetSymbolAddress((void**)&h1h,   g_h1_h);
    cudaGetSymbolAddress((void**)&h1l,   g_h1_l);
    cudaGetSymbolAddress((void**)&mlp,   g_mlp);
    cudaGetSymbolAddress((void**)&wh,    g_w_h);
    cudaGetSymbolAddress((void**)&wl,    g_w_l);
    cudaGetSymbolAddress((void**)&bcomb, g_bcomb);

    cudaFuncSetAttribute(mma_gemm<0, false>, cudaFuncAttributeMaxDynamicSharedMemorySize, GEMM_SMEM);
    cudaFuncSetAttribute(mma_gemm<1, false>, cudaFuncAttributeMaxDynamicSharedMemorySize, GEMM_SMEM);
    cudaFuncSetAttribute(mma_gemm<1, true >, cudaFuncAttributeMaxDynamicSharedMemorySize, GEMM_SMEM);
    cudaFuncSetAttribute(ln1_part,  cudaFuncAttributeMaxDynamicSharedMemorySize, LN_SMEM);
    cudaFuncSetAttribute(resid_ln2, cudaFuncAttributeMaxDynamicSharedMemorySize, LN_SMEM);
    cudaFuncSetAttribute(final_add, cudaFuncAttributeMaxDynamicSharedMemorySize, FIN_SMEM);

    // prep: weight split (1 launch) + combined out/proj weight
    cvtw3<<<2816, 256>>>(in_w, fc1_w, fc2_w, wh, wl);
    wcomb<<<256, 256>>>(proj_w, out_w, out_b, proj_b, wh, wl, bcomb);

    ln1_part<<<1024, 256, LN_SMEM>>>(x, n1g, n1b, xnh, xnl);

    // qkv: [65536,768] = xn @ in_w^T
    mma_gemm<0, false><<<dim3(6, 512), 256, GEMM_SMEM>>>(
        xnh, xnl, wh + OFF_INW, wl + OFF_INW, in_b, qkv, nullptr, nullptr, 768, 256);

    attn_kernel<<<dim3(1024, 8), 256>>>(qkv, ath, atl);

    // combined out_w∘proj_w: [65536,256]
    mma_gemm<0, false><<<dim3(2, 512), 256, GEMM_SMEM>>>(
        ath, atl, wh + OFF_CMBW, wl + OFF_CMBW, bcomb, attn2, nullptr, nullptr, 256, 256);

    resid_ln2<<<1024, 256, LN_SMEM>>>(x, attn2, n2g, n2b, yb, zh, zl);

    // fc1 + gelu: [65536,1024]
    mma_gemm<1, true><<<dim3(8, 512), 256, GEMM_SMEM>>>(
        zh, zl, wh + OFF_FC1W, wl + OFF_FC1W, fc1_b, nullptr, h1h, h1l, 1024, 256);

    // fc2: [65536,256], K=1024
    mma_gemm<0, false><<<dim3(2, 512), 256, GEMM_SMEM>>>(
        h1h, h1l, wh + OFF_FC2W, wl + OFF_FC2W, fc2_b, mlp, nullptr, nullptr, 256, 1024);

    final_add<<<1024, 256, FIN_SMEM>>>(yb, mlp, out);
}

// round 13
// speedup vs baseline: 1.3057x; 1.3057x over previous
#include <cuda_runtime.h>
#include <cuda_fp16.h>
#include <cstdint>
#include <cstddef>

#define NTOK 65536  // 16 * 64 * 64 tokens

// ---------------- scratch (no allocations allowed) ----------------
__device__ __half g_xn  [(size_t)NTOK * 256];
__device__ float  g_qkv [(size_t)NTOK * 768];
__device__ __half g_at  [(size_t)NTOK * 256];
__device__ float  g_attn2[(size_t)NTOK * 256];
__device__ float  g_y   [(size_t)NTOK * 256];
__device__ __half g_z   [(size_t)NTOK * 256];
__device__ __half g_h1  [(size_t)NTOK * 1024];
__device__ float  g_mlp [(size_t)NTOK * 256];
// fp16 weights: hi + (lo * 2^11). in_w(196608) comb_w(65536) fc1_w(262144) fc2_w(262144)
__device__ __half g_w_h [786432];
__device__ __half g_w_ls[786432];
__device__ float  g_bcomb[256];

#define OFF_INW  0
#define OFF_CMBW 196608
#define OFF_FC1W 262144
#define OFF_FC2W 524288

// ---------------- small helpers ----------------
// weight split: hi fp16 + residual scaled by 2^11 (normal range, no denormals)
__device__ __forceinline__ void splitw(float v, __half& h, __half& ls) {
    h = __float2half(v);
    ls = __float2half((v - __half2float(h)) * 2048.0f);
}

__device__ __forceinline__ uint32_t smem_u32(const void* p) {
    uint32_t a;
    asm("{ .reg .u64 t; cvta.to.shared.u64 t, %1; cvt.u32.u64 %0, t; }" : "=r"(a) : "l"(p));
    return a;
}

#define CPA16(dst, src) \
    asm volatile("cp.async.cg.shared.global [%0], [%1], 16;\n" :: "r"(dst), "l"(src))
#define CPA_COMMIT() asm volatile("cp.async.commit_group;\n" ::: "memory")
#define CPA_WAIT1()  asm volatile("cp.async.wait_group 1;\n" ::: "memory")
#define CPA_WAIT0()  asm volatile("cp.async.wait_group 0;\n" ::: "memory")

__device__ __forceinline__ void ldsm4(uint32_t* r, uint32_t addr) {
    asm volatile("ldmatrix.sync.aligned.m8n8.x4.shared.b16 {%0,%1,%2,%3}, [%4];\n"
                 : "=r"(r[0]), "=r"(r[1]), "=r"(r[2]), "=r"(r[3]) : "r"(addr));
}
__device__ __forceinline__ void mma16816(float* c, const uint32_t* a, uint32_t b0, uint32_t b1) {
    asm volatile(
        "mma.sync.aligned.m16n8k16.row.col.f32.f16.f16.f32 "
        "{%0,%1,%2,%3}, {%4,%5,%6,%7}, {%8,%9}, {%0,%1,%2,%3};\n"
        : "+f"(c[0]), "+f"(c[1]), "+f"(c[2]), "+f"(c[3])
        : "r"(a[0]), "r"(a[1]), "r"(a[2]), "r"(a[3]), "r"(b0), "r"(b1));
}
// scale 4 packed-fp16-pair regs by 2^-11 (0x1000 in fp16) — exact exponent shift
__device__ __forceinline__ void hscale4(uint32_t* r) {
    asm("mul.rn.f16x2 %0, %0, %4;\n\t"
        "mul.rn.f16x2 %1, %1, %4;\n\t"
        "mul.rn.f16x2 %2, %2, %4;\n\t"
        "mul.rn.f16x2 %3, %3, %4;"
        : "+r"(r[0]), "+r"(r[1]), "+r"(r[2]), "+r"(r[3]) : "r"(0x10001000u));
}

// ---------------- mma.sync asymmetric-fp16 GEMM ----------------
// C[M,N] = A[M,K] @ B[N,K]^T + bias. A single fp16; B = Bh + Bls*2^-11.
// Pass0: A*Bh ; then fragments scaled in-register by 2^-11 ; Pass1: (A>>11)*Bls.
// Block 128x128, 8 warps (2x4), warp tile 64x32, BK=32, cp.async double buffer.
// smem tile: 128 rows x 80B (64B data + 16B pad) -> ldmatrix conflict-free.
// Stage = A|Bh|Bls = 30KB; 2 stages = 60KB; 2 CTA/SM enforced.
#define ROW_B       80
#define TILE_B      (128 * ROW_B)     // 10240
#define STAGE_B     (3 * TILE_B)      // 30720
#define GEMM_SMEM   (2 * STAGE_B)     // 61440

template <int OUTMODE /*0=f32, 1=fp16*/, bool GELU>
__global__ __launch_bounds__(256, 2)
void mma_gemm(const __half* __restrict__ A,
              const __half* __restrict__ Bh, const __half* __restrict__ Bl,
              const float* __restrict__ bias,
              float* __restrict__ Cf, __half* __restrict__ Ch,
              int N, int K) {
    extern __shared__ char smem[];
    const uint32_t sb0 = smem_u32(smem);
    const int tid = threadIdx.x, lane = tid & 31, wid = tid >> 5;
    const int wm = wid >> 2, wn = wid & 3;        // 2 x 4 warp grid
    const int bm = blockIdx.y * 128, bn = blockIdx.x * 128;

    float acc[4][4][4];
#pragma unroll
    for (int i = 0; i < 4; i++)
#pragma unroll
        for (int j = 0; j < 4; j++)
#pragma unroll
            for (int k = 0; k < 4; k++) acc[i][j][k] = 0.f;

    const int nc = K >> 5;  // BK=32 chunks

    auto load_stage = [&](int c, int s) {
        const uint32_t base = sb0 + s * STAGE_B;
        const size_t k0 = (size_t)c << 5;
#pragma unroll
        for (int it = 0; it < 2; ++it) {
            int e = it * 256 + tid;
            int row = e >> 2, ch = e & 3;
            uint32_t d = base + row * ROW_B + ch * 16;
            size_t ga = ((size_t)(bm + row) * K + k0 + ch * 8) * 2;
            size_t gb = ((size_t)(bn + row) * K + k0 + ch * 8) * 2;
            CPA16(d,              (const char*)A  + ga);
            CPA16(d + TILE_B,     (const char*)Bh + gb);
            CPA16(d + 2 * TILE_B, (const char*)Bl + gb);
        }
        CPA_COMMIT();
    };

    load_stage(0, 0);

    // per-warp ldmatrix base offsets (within a tile)
    const uint32_t a_off = (uint32_t)((wm * 64 + (lane & 15)) * ROW_B + (lane >> 4) * 16);
    const uint32_t b_off = (uint32_t)((wn * 32 + (lane & 7) + ((lane >> 4) << 3)) * ROW_B +
                                      ((lane >> 3) & 1) * 16);

    for (int c = 0; c < nc; ++c) {
        const int s = c & 1;
        if (c + 1 < nc) { load_stage(c + 1, (c + 1) & 1); CPA_WAIT1(); }
        else            { CPA_WAIT0(); }
        __syncthreads();

        const uint32_t base = sb0 + s * STAGE_B;
        const uint32_t ab = base + a_off;
        const uint32_t bb = base + TILE_B + b_off;
#pragma unroll
        for (int ks = 0; ks < 2; ++ks) {
            uint32_t a[4][4], bh[2][4], bl[2][4];
#pragma unroll
            for (int mf = 0; mf < 4; ++mf) ldsm4(a[mf], ab + mf * 16 * ROW_B + ks * 32);
#pragma unroll
            for (int nf = 0; nf < 2; ++nf) ldsm4(bh[nf], bb + nf * 16 * ROW_B + ks * 32);
#pragma unroll
            for (int nf = 0; nf < 2; ++nf) ldsm4(bl[nf], bb + TILE_B + nf * 16 * ROW_B + ks * 32);
            // pass 0: A * Bh ; scale a[mf] by 2^-11 right after its last pass-0 use
#pragma unroll
            for (int mf = 0; mf < 4; ++mf) {
#pragma unroll
                for (int nf = 0; nf < 2; ++nf)
#pragma unroll
                    for (int sub = 0; sub < 2; ++sub)
                        mma16816(acc[mf][nf * 2 + sub], a[mf],
                                 bh[nf][sub * 2], bh[nf][sub * 2 + 1]);
                hscale4(a[mf]);
            }
            // pass 1: (A*2^-11) * (Bl*2^11) == A * Bl
#pragma unroll
            for (int mf = 0; mf < 4; ++mf)
#pragma unroll
                for (int nf = 0; nf < 2; ++nf)
#pragma unroll
                    for (int sub = 0; sub < 2; ++sub)
                        mma16816(acc[mf][nf * 2 + sub], a[mf],
                                 bl[nf][sub * 2], bl[nf][sub * 2 + 1]);
        }
        __syncthreads();
    }

    // epilogue straight from fragments
#pragma unroll
    for (int mf = 0; mf < 4; ++mf) {
#pragma unroll
        for (int nf8 = 0; nf8 < 4; ++nf8) {
            int row = bm + wm * 64 + mf * 16 + (lane >> 2);
            int col = bn + wn * 32 + nf8 * 8 + (lane & 3) * 2;
            float b0 = bias[col], b1 = bias[col + 1];
#pragma unroll
            for (int half_ = 0; half_ < 2; ++half_) {
                int r = row + half_ * 8;
                float v0 = acc[mf][nf8][half_ * 2 + 0] + b0;
                float v1 = acc[mf][nf8][half_ * 2 + 1] + b1;
                if (GELU) { v0 = v0 * normcdff(v0); v1 = v1 * normcdff(v1); }
                size_t o = (size_t)r * N + col;
                if (OUTMODE == 0) {
                    *(float2*)(Cf + o) = make_float2(v0, v1);
                } else {
                    *(__half2*)(Ch + o) = __floats2half2_rn(v0, v1);
                }
            }
        }
    }
}

// ---------------- weight fp32 -> fp16 (hi, lo*2^11), 3 segments in one launch ----
__global__ void cvtw3(const float* __restrict__ in_w, const float* __restrict__ fc1_w,
                      const float* __restrict__ fc2_w,
                      __half* __restrict__ wh, __half* __restrict__ wls) {
    int i = blockIdx.x * 256 + threadIdx.x;  // 0 .. 720895
    const float* src; int dst;
    if (i < 196608)      { src = in_w;  dst = OFF_INW  + i; }
    else if (i < 458752) { src = fc1_w - 196608; dst = OFF_FC1W + (i - 196608); }
    else                 { src = fc2_w - 458752; dst = OFF_FC2W + (i - 458752); }
    __half hh, ll;
    splitw(src[i], hh, ll);
    wh[dst] = hh; wls[dst] = ll;
}

// ---------------- combined out∘proj weight: W = proj_w @ out_w ----------------
__global__ void wcomb(const float* __restrict__ proj_w, const float* __restrict__ out_w,
                      const float* __restrict__ out_b, const float* __restrict__ proj_b,
                      __half* __restrict__ wh, __half* __restrict__ wls,
                      float* __restrict__ bcomb) {
    int i = blockIdx.x;       // output row
    int j = threadIdx.x;      // output col (coalesced over out_w)
    float s = 0.f;
    for (int k = 0; k < 256; ++k)
        s += proj_w[i * 256 + k] * out_w[k * 256 + j];
    __half hh, ll; splitw(s, hh, ll);
    wh[OFF_CMBW + i * 256 + j] = hh;
    wls[OFF_CMBW + i * 256 + j] = ll;
    if (j == 0) {
        float b = proj_b[i];
        for (int k = 0; k < 256; ++k) b += proj_w[i * 256 + k] * out_b[k];
        bcomb[i] = b;
    }
}

// (b,h,w) -> token index T in shifted-window order
__device__ __forceinline__ int src_to_token(int b, int h, int w) {
    int hs = (h + 60) & 63, ws = (w + 60) & 63;
    return ((b * 8 + (hs >> 3)) * 8 + (ws >> 3)) * 64 + (hs & 7) * 8 + (ws & 7);
}

// ---------------- LN1 + shift + window partition -> fp16 ----------------
#define LN_SMEM (256 * 65 * 4)
__global__ __launch_bounds__(256)
void ln1_part(const float* __restrict__ x,
              const float* __restrict__ g, const float* __restrict__ bb,
              __half* __restrict__ o) {
    extern __shared__ float xs[];  // [256][65]
    int b = blockIdx.x >> 6, h = blockIdx.x & 63;
    int tid = threadIdx.x;
    const float* xp = x + (size_t)b * 1048576 + h * 64;
#pragma unroll
    for (int it = 0; it < 64; ++it) {
        int e = it * 256 + tid;
        int c = e >> 6, w = e & 63;
        xs[c * 65 + w] = xp[(size_t)c * 4096 + w];
    }
    __syncthreads();
    int warp = tid >> 5, lane = tid & 31;
#pragma unroll 1
    for (int t = 0; t < 8; ++t) {
        int w = t * 8 + warp;
        float v[8]; float s = 0.f;
#pragma unroll
        for (int k = 0; k < 8; k++) { v[k] = xs[(k * 32 + lane) * 65 + w]; s += v[k]; }
#pragma unroll
        for (int o2 = 16; o2; o2 >>= 1) s += __shfl_xor_sync(0xffffffffu, s, o2);
        float mu = s * 0.00390625f;
        float q = 0.f;
#pragma unroll
        for (int k = 0; k < 8; k++) { float d = v[k] - mu; q += d * d; }
#pragma unroll
        for (int o2 = 16; o2; o2 >>= 1) q += __shfl_xor_sync(0xffffffffu, q, o2);
        float rs = rsqrtf(q * 0.00390625f + 1e-6f);
        size_t tb = (size_t)src_to_token(b, h, w) * 256;
#pragma unroll
        for (int k = 0; k < 8; k++) {
            int c = k * 32 + lane;
            o[tb + c] = __float2half((v[k] - mu) * rs * g[c] + bb[c]);
        }
    }
}

// ---------------- attention: one block per (window, head) — R10-proven form ----
__global__ __launch_bounds__(256)
void attn_kernel(const float* __restrict__ qkv, __half* __restrict__ oh) {
    __shared__ __align__(16) float Qs[64][33];
    __shared__ __align__(16) float Ks[64][33];
    __shared__ __align__(16) float Vs[64][36];
    __shared__ float S[64][65];
    __shared__ float rinv[64];
    int win = blockIdx.x, head = blockIdx.y;
    int tid = threadIdx.x;
    size_t base = (size_t)win * 64 * 768 + head * 32;

#pragma unroll
    for (int e = tid; e < 512; e += 256) {
        int i = e >> 3, f4 = e & 7, d = f4 * 4;
        const float* rp = qkv + base + (size_t)i * 768;
        float4 q = *((const float4*)rp + f4);
        float4 k = *((const float4*)(rp + 256) + f4);
        float4 v = *((const float4*)(rp + 512) + f4);
        Qs[i][d] = q.x; Qs[i][d+1] = q.y; Qs[i][d+2] = q.z; Qs[i][d+3] = q.w;
        Ks[i][d] = k.x; Ks[i][d+1] = k.y; Ks[i][d+2] = k.z; Ks[i][d+3] = k.w;
        Vs[i][d] = v.x; Vs[i][d+1] = v.y; Vs[i][d+2] = v.z; Vs[i][d+3] = v.w;
    }
    __syncthreads();

    // QK^T, 4x4 per thread (16x16 thread grid)
    {
        int ti = (tid >> 4) * 4, tj = (tid & 15) * 4;
        float s[4][4];
#pragma unroll
        for (int r = 0; r < 4; ++r)
#pragma unroll
            for (int c2 = 0; c2 < 4; ++c2) s[r][c2] = 0.f;
#pragma unroll
        for (int d = 0; d < 32; ++d) {
            float qv[4], kv[4];
#pragma unroll
            for (int r = 0; r < 4; ++r) qv[r] = Qs[ti + r][d];
#pragma unroll
            for (int c2 = 0; c2 < 4; ++c2) kv[c2] = Ks[tj + c2][d];
#pragma unroll
            for (int r = 0; r < 4; ++r)
#pragma unroll
                for (int c2 = 0; c2 < 4; ++c2) s[r][c2] += qv[r] * kv[c2];
        }
        const float scale = 0.17677669529663687f;  // 1/sqrt(32)
#pragma unroll
        for (int r = 0; r < 4; ++r)
#pragma unroll
            for (int c2 = 0; c2 < 4; ++c2) S[ti + r][tj + c2] = s[r][c2] * scale;
    }
    __syncthreads();

    // softmax: 4 lanes per row, 16 cols each
    {
        int row = tid >> 2, j0 = (tid & 3) * 16;
        float m = -1e30f;
#pragma unroll
        for (int k = 0; k < 16; ++k) m = fmaxf(m, S[row][j0 + k]);
        m = fmaxf(m, __shfl_xor_sync(0xffffffffu, m, 1));
        m = fmaxf(m, __shfl_xor_sync(0xffffffffu, m, 2));
        float sum = 0.f;
#pragma unroll
        for (int k = 0; k < 16; ++k) {
            float e = __expf(S[row][j0 + k] - m);
            S[row][j0 + k] = e; sum += e;
        }
        sum += __shfl_xor_sync(0xffffffffu, sum, 1);
        sum += __shfl_xor_sync(0xffffffffu, sum, 2);
        if ((tid & 3) == 0) rinv[row] = 1.f / sum;
    }
    __syncthreads();

    // SV: 2 rows x 4 cols per thread
    {
        int r0 = (tid >> 3) * 2, dc = (tid & 7) * 4;
        float a0[4] = {0.f, 0.f, 0.f, 0.f}, a1[4] = {0.f, 0.f, 0.f, 0.f};
#pragma unroll
        for (int j = 0; j < 64; ++j) {
            float s0 = S[r0][j], s1 = S[r0 + 1][j];
            float4 v = *(const float4*)&Vs[j][dc];
            a0[0] += s0 * v.x; a0[1] += s0 * v.y; a0[2] += s0 * v.z; a0[3] += s0 * v.w;
            a1[0] += s1 * v.x; a1[1] += s1 * v.y; a1[2] += s1 * v.z; a1[3] += s1 * v.w;
        }
        float ri0 = rinv[r0], ri1 = rinv[r0 + 1];
        size_t o0 = (size_t)(win * 64 + r0) * 256 + head * 32 + dc;
#pragma unroll
        for (int c2 = 0; c2 < 4; ++c2) {
            oh[o0 + c2]       = __float2half(a0[c2] * ri0);
            oh[o0 + 256 + c2] = __float2half(a1[c2] * ri1);
        }
    }
}

// ---------------- window reverse + residual + LN2 ----------------
__global__ __launch_bounds__(256)
void resid_ln2(const float* __restrict__ x, const float* __restrict__ a,
               const float* __restrict__ g, const float* __restrict__ bb,
               float* __restrict__ yout, __half* __restrict__ zout) {
    extern __shared__ float xs[];  // [256][65]
    int b = blockIdx.x >> 6, h = blockIdx.x & 63;
    int tid = threadIdx.x;
    const float* xp = x + (size_t)b * 1048576 + h * 64;
#pragma unroll
    for (int it = 0; it < 64; ++it) {
        int e = it * 256 + tid;
        int c = e >> 6, w = e & 63;
        xs[c * 65 + w] = xp[(size_t)c * 4096 + w];
    }
    __syncthreads();
    int warp = tid >> 5, lane = tid & 31;
#pragma unroll 1
    for (int t = 0; t < 8; ++t) {
        int w = t * 8 + warp;
        size_t tb = (size_t)src_to_token(b, h, w) * 256;
        float v[8]; float s = 0.f;
#pragma unroll
        for (int k = 0; k < 8; k++) {
            int c = k * 32 + lane;
            v[k] = xs[c * 65 + w] + a[tb + c];
            s += v[k];
        }
#pragma unroll
        for (int o2 = 16; o2; o2 >>= 1) s += __shfl_xor_sync(0xffffffffu, s, o2);
        float mu = s * 0.00390625f;
        float q = 0.f;
#pragma unroll
        for (int k = 0; k < 8; k++) { float d = v[k] - mu; q += d * d; }
#pragma unroll
        for (int o2 = 16; o2; o2 >>= 1) q += __shfl_xor_sync(0xffffffffu, q, o2);
        float rs = rsqrtf(q * 0.00390625f + 1e-6f);
#pragma unroll
        for (int k = 0; k < 8; k++) {
            int c = k * 32 + lane;
            yout[tb + c] = v[k];
            zout[tb + c] = __float2half((v[k] - mu) * rs * g[c] + bb[c]);
        }
    }
}

// ---------------- final: out[b,c,h,w] = y_tok + mlp_tok, smem transpose ----
#define FIN_SMEM (64 * 257 * 4)
__global__ __launch_bounds__(256)
void final_add(const float* __restrict__ y, const float* __restrict__ m,
               float* __restrict__ out) {
    extern __shared__ float ss[];  // [64 tokens][257]
    int b = blockIdx.x >> 6, h = blockIdx.x & 63;
    int tid = threadIdx.x;
    int warp = tid >> 5, lane = tid & 31;
#pragma unroll 1
    for (int t = 0; t < 8; ++t) {
        int w = t * 8 + warp;
        size_t tb = (size_t)src_to_token(b, h, w) * 256;
#pragma unroll
        for (int k = 0; k < 8; k++) {
            int c = k * 32 + lane;
            ss[w * 257 + c] = y[tb + c] + m[tb + c];
        }
    }
    __syncthreads();
    float* op = out + (size_t)b * 1048576 + h * 64;
#pragma unroll
    for (int it = 0; it < 64; ++it) {
        int e = it * 256 + tid;
        int c = e >> 6, w = e & 63;
        op[(size_t)c * 4096 + w] = ss[w * 257 + c];
    }
}

// ---------------- launch ----------------
extern "C" void kernel_launch(void* const* d_in, const int* in_sizes, int n_in,
                              void* d_out, int out_size) {
    const float* x      = (const float*)d_in[0];
    const float* n1g    = (const float*)d_in[1];
    const float* n1b    = (const float*)d_in[2];
    const float* in_w   = (const float*)d_in[3];
    const float* in_b   = (const float*)d_in[4];
    const float* out_w  = (const float*)d_in[5];
    const float* out_b  = (const float*)d_in[6];
    const float* proj_w = (const float*)d_in[7];
    const float* proj_b = (const float*)d_in[8];
    const float* n2g    = (const float*)d_in[9];
    const float* n2b    = (const float*)d_in[10];
    const float* fc1_w  = (const float*)d_in[11];
    const float* fc1_b  = (const float*)d_in[12];
    const float* fc2_w  = (const float*)d_in[13];
    const float* fc2_b  = (const float*)d_in[14];
    float* out = (float*)d_out;

    __half *xn, *at, *zb2, *h1, *wh, *wls;
    float *qkv, *attn2, *yb, *mlp, *bcomb;
    cudaGetSymbolAddress((void**)&xn,    g_xn);
    cudaGetSymbolAddress((void**)&qkv,   g_qkv);
    cudaGetSymbolAddress((void**)&at,    g_at);
    cudaGetSymbolAddress((void**)&attn2, g_attn2);
    cudaGetSymbolAddress((void**)&yb,    g_y);
    cudaGetSymbolAddress((void**)&zb2,   g_z);
    cudaGetSymbolAddress((void**)&h1,    g_h1);
    cudaGetSymbolAddress((void**)&mlp,   g_mlp);
    cudaGetSymbolAddress((void**)&wh,    g_w_h);
    cudaGetSymbolAddress((void**)&wls,   g_w_ls);
    cudaGetSymbolAddress((void**)&bcomb, g_bcomb);

    cudaFuncSetAttribute(mma_gemm<0, false>, cudaFuncAttributeMaxDynamicSharedMemorySize, GEMM_SMEM);
    cudaFuncSetAttribute(mma_gemm<1, false>, cudaFuncAttributeMaxDynamicSharedMemorySize, GEMM_SMEM);
    cudaFuncSetAttribute(mma_gemm<1, true >, cudaFuncAttributeMaxDynamicSharedMemorySize, GEMM_SMEM);
    cudaFuncSetAttribute(ln1_part,  cudaFuncAttributeMaxDynamicSharedMemorySize, LN_SMEM);
    cudaFuncSetAttribute(resid_ln2, cudaFuncAttributeMaxDynamicSharedMemorySize, LN_SMEM);
    cudaFuncSetAttribute(final_add, cudaFuncAttributeMaxDynamicSharedMemorySize, FIN_SMEM);

    // prep: weight split (1 launch) + combined out/proj weight
    cvtw3<<<2816, 256>>>(in_w, fc1_w, fc2_w, wh, wls);
    wcomb<<<256, 256>>>(proj_w, out_w, out_b, proj_b, wh, wls, bcomb);

    ln1_part<<<1024, 256, LN_SMEM>>>(x, n1g, n1b, xn);

    // qkv: [65536,768] = xn @ in_w^T
    mma_gemm<0, false><<<dim3(6, 512), 256, GEMM_SMEM>>>(
        xn, wh + OFF_INW, wls + OFF_INW, in_b, qkv, nullptr, 768, 256);

    attn_kernel<<<dim3(1024, 8), 256>>>(qkv, at);

    // combined out_w∘proj_w: [65536,256]
    mma_gemm<0, false><<<dim3(2, 512), 256, GEMM_SMEM>>>(
        at, wh + OFF_CMBW, wls + OFF_CMBW, bcomb, attn2, nullptr, 256, 256);

    resid_ln2<<<1024, 256, LN_SMEM>>>(x, attn2, n2g, n2b, yb, zb2);

    // fc1 + gelu: [65536,1024]
    mma_gemm<1, true><<<dim3(8, 512), 256, GEMM_SMEM>>>(
        zb2, wh + OFF_FC1W, wls + OFF_FC1W, fc1_b, nullptr, h1, 1024, 256);

    // fc2: [65536,256], K=1024
    mma_gemm<0, false><<<dim3(2, 512), 256, GEMM_SMEM>>>(
        h1, wh + OFF_FC2W, wls + OFF_FC2W, fc2_b, mlp, nullptr, 256, 1024);

    final_add<<<1024, 256, FIN_SMEM>>>(yb, mlp, out);
}

// round 14
// speedup vs baseline: 1.3161x; 1.0080x over previous
#include <cuda_runtime.h>
#include <cuda_fp16.h>
#include <cstdint>
#include <cstddef>

#define NTOK 65536  // 16 * 64 * 64 tokens

// ---------------- scratch (no allocations allowed) ----------------
__device__ __half g_xn  [(size_t)NTOK * 256];
__device__ __half g_qkv [(size_t)NTOK * 768];
__device__ __half g_at  [(size_t)NTOK * 256];
__device__ float  g_attn2[(size_t)NTOK * 256];
__device__ float  g_y   [(size_t)NTOK * 256];
__device__ __half g_z   [(size_t)NTOK * 256];
__device__ __half g_h1  [(size_t)NTOK * 1024];
__device__ float  g_mlp [(size_t)NTOK * 256];
// fp16 weights: hi + (lo * 2^11). in_w(196608) comb_w(65536) fc1_w(262144) fc2_w(262144)
__device__ __half g_w_h [786432];
__device__ __half g_w_ls[786432];
__device__ float  g_bcomb[256];

#define OFF_INW  0
#define OFF_CMBW 196608
#define OFF_FC1W 262144
#define OFF_FC2W 524288

// ---------------- small helpers ----------------
// weight split: hi fp16 + residual scaled by 2^11 (normal range, no denormals)
__device__ __forceinline__ void splitw(float v, __half& h, __half& ls) {
    h = __float2half(v);
    ls = __float2half((v - __half2float(h)) * 2048.0f);
}

__device__ __forceinline__ uint32_t smem_u32(const void* p) {
    uint32_t a;
    asm("{ .reg .u64 t; cvta.to.shared.u64 t, %1; cvt.u32.u64 %0, t; }" : "=r"(a) : "l"(p));
    return a;
}

#define CPA16(dst, src) \
    asm volatile("cp.async.cg.shared.global [%0], [%1], 16;\n" :: "r"(dst), "l"(src))
#define CPA_COMMIT() asm volatile("cp.async.commit_group;\n" ::: "memory")
#define CPA_WAIT1()  asm volatile("cp.async.wait_group 1;\n" ::: "memory")

__device__ __forceinline__ void ldsm4(uint32_t* r, uint32_t addr) {
    asm volatile("ldmatrix.sync.aligned.m8n8.x4.shared.b16 {%0,%1,%2,%3}, [%4];\n"
                 : "=r"(r[0]), "=r"(r[1]), "=r"(r[2]), "=r"(r[3]) : "r"(addr));
}
__device__ __forceinline__ void mma16816(float* c, const uint32_t* a, uint32_t b0, uint32_t b1) {
    asm volatile(
        "mma.sync.aligned.m16n8k16.row.col.f32.f16.f16.f32 "
        "{%0,%1,%2,%3}, {%4,%5,%6,%7}, {%8,%9}, {%0,%1,%2,%3};\n"
        : "+f"(c[0]), "+f"(c[1]), "+f"(c[2]), "+f"(c[3])
        : "r"(a[0]), "r"(a[1]), "r"(a[2]), "r"(a[3]), "r"(b0), "r"(b1));
}
// scale 4 packed-fp16-pair regs by 2^-11 (0x1000 in fp16) — exact exponent shift
__device__ __forceinline__ void hscale4(uint32_t* r) {
    asm("mul.rn.f16x2 %0, %0, %4;\n\t"
        "mul.rn.f16x2 %1, %1, %4;\n\t"
        "mul.rn.f16x2 %2, %2, %4;\n\t"
        "mul.rn.f16x2 %3, %3, %4;"
        : "+r"(r[0]), "+r"(r[1]), "+r"(r[2]), "+r"(r[3]) : "r"(0x10001000u));
}

// ---------------- mma.sync asymmetric-fp16 GEMM ----------------
// C[M,N] = A[M,K] @ B[N,K]^T + bias. A single fp16; B = Bh + Bls*2^-11.
// Pass0: A*Bh ; fragments scaled in-register by 2^-11 ; Pass1: (A>>11)*Bls.
// Block 128x128, 8 warps (2x4), warp tile 64x32, BK=32.
// 3-stage cp.async pipeline, ONE __syncthreads per chunk (hazard-safe: load(c+2)
// writes stage (c-1)%3, which the sync proves fully consumed), 2 CTA/SM held.
// smem tile: 128 rows x 80B (64B data + 16B pad) -> ldmatrix conflict-free.
#define ROW_B       80
#define TILE_B      (128 * ROW_B)     // 10240
#define STAGE_B     (3 * TILE_B)      // 30720 (A | Bh | Bls)
#define GEMM_SMEM   (3 * STAGE_B)     // 92160 ; 2 CTAs = 184320 <= 228KB

template <int OUTMODE /*0=f32, 1=fp16*/, bool GELU>
__global__ __launch_bounds__(256, 2)
void mma_gemm(const __half* __restrict__ A,
              const __half* __restrict__ Bh, const __half* __restrict__ Bl,
              const float* __restrict__ bias,
              float* __restrict__ Cf, __half* __restrict__ Ch,
              int N, int K) {
    extern __shared__ char smem[];
    const uint32_t sb0 = smem_u32(smem);
    const int tid = threadIdx.x, lane = tid & 31, wid = tid >> 5;
    const int wm = wid >> 2, wn = wid & 3;        // 2 x 4 warp grid
    const int bm = blockIdx.y * 128, bn = blockIdx.x * 128;

    float acc[4][4][4];
#pragma unroll
    for (int i = 0; i < 4; i++)
#pragma unroll
        for (int j = 0; j < 4; j++)
#pragma unroll
            for (int k = 0; k < 4; k++) acc[i][j][k] = 0.f;

    const int nc = K >> 5;  // BK=32 chunks

    auto load_stage = [&](int c, int s) {
        const uint32_t base = sb0 + s * STAGE_B;
        const size_t k0 = (size_t)c << 5;
#pragma unroll
        for (int it = 0; it < 2; ++it) {
            int e = it * 256 + tid;
            int row = e >> 2, ch = e & 3;
            uint32_t d = base + row * ROW_B + ch * 16;
            size_t ga = ((size_t)(bm + row) * K + k0 + ch * 8) * 2;
            size_t gb = ((size_t)(bn + row) * K + k0 + ch * 8) * 2;
            CPA16(d,              (const char*)A  + ga);
            CPA16(d + TILE_B,     (const char*)Bh + gb);
            CPA16(d + 2 * TILE_B, (const char*)Bl + gb);
        }
        CPA_COMMIT();
    };

    load_stage(0, 0);
    load_stage(1, 1);

    // per-warp ldmatrix base offsets (within a tile)
    const uint32_t a_off = (uint32_t)((wm * 64 + (lane & 15)) * ROW_B + (lane >> 4) * 16);
    const uint32_t b_off = (uint32_t)((wn * 32 + (lane & 7) + ((lane >> 4) << 3)) * ROW_B +
                                      ((lane >> 3) & 1) * 16);

    for (int c = 0; c < nc; ++c) {
        CPA_WAIT1();          // stage c arrived (<=1 group pending)
        __syncthreads();      // all warps done reading stage (c-1)%3
        if (c + 2 < nc) load_stage(c + 2, (c + 2) % 3);

        const uint32_t base = sb0 + (c % 3) * STAGE_B;
        const uint32_t ab = base + a_off;
        const uint32_t bb = base + TILE_B + b_off;
#pragma unroll
        for (int ks = 0; ks < 2; ++ks) {
            uint32_t a[4][4], bh[2][4], bl[2][4];
#pragma unroll
            for (int mf = 0; mf < 4; ++mf) ldsm4(a[mf], ab + mf * 16 * ROW_B + ks * 32);
#pragma unroll
            for (int nf = 0; nf < 2; ++nf) ldsm4(bh[nf], bb + nf * 16 * ROW_B + ks * 32);
#pragma unroll
            for (int nf = 0; nf < 2; ++nf) ldsm4(bl[nf], bb + TILE_B + nf * 16 * ROW_B + ks * 32);
            // pass 0: A * Bh ; scale a[mf] by 2^-11 right after its last pass-0 use
#pragma unroll
            for (int mf = 0; mf < 4; ++mf) {
#pragma unroll
                for (int nf = 0; nf < 2; ++nf)
#pragma unroll
                    for (int sub = 0; sub < 2; ++sub)
                        mma16816(acc[mf][nf * 2 + sub], a[mf],
                                 bh[nf][sub * 2], bh[nf][sub * 2 + 1]);
                hscale4(a[mf]);
            }
            // pass 1: (A*2^-11) * (Bl*2^11) == A * Bl
#pragma unroll
            for (int mf = 0; mf < 4; ++mf)
#pragma unroll
                for (int nf = 0; nf < 2; ++nf)
#pragma unroll
                    for (int sub = 0; sub < 2; ++sub)
                        mma16816(acc[mf][nf * 2 + sub], a[mf],
                                 bl[nf][sub * 2], bl[nf][sub * 2 + 1]);
        }
    }

    // epilogue straight from fragments
#pragma unroll
    for (int mf = 0; mf < 4; ++mf) {
#pragma unroll
        for (int nf8 = 0; nf8 < 4; ++nf8) {
            int row = bm + wm * 64 + mf * 16 + (lane >> 2);
            int col = bn + wn * 32 + nf8 * 8 + (lane & 3) * 2;
            float b0 = bias[col], b1 = bias[col + 1];
#pragma unroll
            for (int half_ = 0; half_ < 2; ++half_) {
                int r = row + half_ * 8;
                float v0 = acc[mf][nf8][half_ * 2 + 0] + b0;
                float v1 = acc[mf][nf8][half_ * 2 + 1] + b1;
                if (GELU) { v0 = v0 * normcdff(v0); v1 = v1 * normcdff(v1); }
                size_t o = (size_t)r * N + col;
                if (OUTMODE == 0) {
                    *(float2*)(Cf + o) = make_float2(v0, v1);
                } else {
                    *(__half2*)(Ch + o) = __floats2half2_rn(v0, v1);
                }
            }
        }
    }
}

// ---------------- weight fp32 -> fp16 (hi, lo*2^11), 3 segments in one launch ----
__global__ void cvtw3(const float* __restrict__ in_w, const float* __restrict__ fc1_w,
                      const float* __restrict__ fc2_w,
                      __half* __restrict__ wh, __half* __restrict__ wls) {
    int i = blockIdx.x * 256 + threadIdx.x;  // 0 .. 720895
    const float* src; int dst;
    if (i < 196608)      { src = in_w;  dst = OFF_INW  + i; }
    else if (i < 458752) { src = fc1_w - 196608; dst = OFF_FC1W + (i - 196608); }
    else                 { src = fc2_w - 458752; dst = OFF_FC2W + (i - 458752); }
    __half hh, ll;
    splitw(src[i], hh, ll);
    wh[dst] = hh; wls[dst] = ll;
}

// ---------------- combined out∘proj weight: W = proj_w @ out_w ----------------
__global__ void wcomb(const float* __restrict__ proj_w, const float* __restrict__ out_w,
                      const float* __restrict__ out_b, const float* __restrict__ proj_b,
                      __half* __restrict__ wh, __half* __restrict__ wls,
                      float* __restrict__ bcomb) {
    int i = blockIdx.x;       // output row
    int j = threadIdx.x;      // output col (coalesced over out_w)
    float s = 0.f;
    for (int k = 0; k < 256; ++k)
        s += proj_w[i * 256 + k] * out_w[k * 256 + j];
    __half hh, ll; splitw(s, hh, ll);
    wh[OFF_CMBW + i * 256 + j] = hh;
    wls[OFF_CMBW + i * 256 + j] = ll;
    if (j == 0) {
        float b = proj_b[i];
        for (int k = 0; k < 256; ++k) b += proj_w[i * 256 + k] * out_b[k];
        bcomb[i] = b;
    }
}

// (b,h,w) -> token index T in shifted-window order
__device__ __forceinline__ int src_to_token(int b, int h, int w) {
    int hs = (h + 60) & 63, ws = (w + 60) & 63;
    return ((b * 8 + (hs >> 3)) * 8 + (ws >> 3)) * 64 + (hs & 7) * 8 + (ws & 7);
}

// ---------------- LN1 + shift + window partition -> fp16 ----------------
#define LN_SMEM (256 * 65 * 4)
__global__ __launch_bounds__(256)
void ln1_part(const float* __restrict__ x,
              const float* __restrict__ g, const float* __restrict__ bb,
              __half* __restrict__ o) {
    extern __shared__ float xs[];  // [256][65]
    int b = blockIdx.x >> 6, h = blockIdx.x & 63;
    int tid = threadIdx.x;
    const float* xp = x + (size_t)b * 1048576 + h * 64;
#pragma unroll
    for (int it = 0; it < 64; ++it) {
        int e = it * 256 + tid;
        int c = e >> 6, w = e & 63;
        xs[c * 65 + w] = xp[(size_t)c * 4096 + w];
    }
    __syncthreads();
    int warp = tid >> 5, lane = tid & 31;
#pragma unroll 1
    for (int t = 0; t < 8; ++t) {
        int w = t * 8 + warp;
        float v[8]; float s = 0.f;
#pragma unroll
        for (int k = 0; k < 8; k++) { v[k] = xs[(k * 32 + lane) * 65 + w]; s += v[k]; }
#pragma unroll
        for (int o2 = 16; o2; o2 >>= 1) s += __shfl_xor_sync(0xffffffffu, s, o2);
        float mu = s * 0.00390625f;
        float q = 0.f;
#pragma unroll
        for (int k = 0; k < 8; k++) { float d = v[k] - mu; q += d * d; }
#pragma unroll
        for (int o2 = 16; o2; o2 >>= 1) q += __shfl_xor_sync(0xffffffffu, q, o2);
        float rs = rsqrtf(q * 0.00390625f + 1e-6f);
        size_t tb = (size_t)src_to_token(b, h, w) * 256;
#pragma unroll
        for (int k = 0; k < 8; k++) {
            int c = k * 32 + lane;
            o[tb + c] = __float2half((v[k] - mu) * rs * g[c] + bb[c]);
        }
    }
}

// ---------------- attention: one block per (window, head) — fp16 qkv input ----
__global__ __launch_bounds__(256)
void attn_kernel(const __half* __restrict__ qkv, __half* __restrict__ oh) {
    __shared__ __align__(16) float Qs[64][33];
    __shared__ __align__(16) float Ks[64][33];
    __shared__ __align__(16) float Vs[64][36];
    __shared__ float S[64][65];
    __shared__ float rinv[64];
    int win = blockIdx.x, head = blockIdx.y;
    int tid = threadIdx.x;
    size_t base = (size_t)win * 64 * 768 + head * 32;

    // load q/k/v: 64 rows x 4 uint4 (8 halfs) each; convert to f32 smem
    {
        int i = tid >> 2, c8 = tid & 3, d = c8 * 8;
        const __half* rp = qkv + base + (size_t)i * 768;
        uint4 qv = *((const uint4*)rp + c8);
        uint4 kv = *((const uint4*)(rp + 256) + c8);
        uint4 vv = *((const uint4*)(rp + 512) + c8);
        const __half2* qh = (const __half2*)&qv;
        const __half2* kh = (const __half2*)&kv;
        const __half2* vh = (const __half2*)&vv;
#pragma unroll
        for (int t = 0; t < 4; ++t) {
            float2 f;
            f = __half22float2(qh[t]); Qs[i][d + 2*t] = f.x; Qs[i][d + 2*t + 1] = f.y;
            f = __half22float2(kh[t]); Ks[i][d + 2*t] = f.x; Ks[i][d + 2*t + 1] = f.y;
            f = __half22float2(vh[t]); Vs[i][d + 2*t] = f.x; Vs[i][d + 2*t + 1] = f.y;
        }
    }
    __syncthreads();

    // QK^T, 4x4 per thread (16x16 thread grid)
    {
        int ti = (tid >> 4) * 4, tj = (tid & 15) * 4;
        float s[4][4];
#pragma unroll
        for (int r = 0; r < 4; ++r)
#pragma unroll
            for (int c2 = 0; c2 < 4; ++c2) s[r][c2] = 0.f;
#pragma unroll
        for (int d = 0; d < 32; ++d) {
            float qv[4], kv[4];
#pragma unroll
            for (int r = 0; r < 4; ++r) qv[r] = Qs[ti + r][d];
#pragma unroll
            for (int c2 = 0; c2 < 4; ++c2) kv[c2] = Ks[tj + c2][d];
#pragma unroll
            for (int r = 0; r < 4; ++r)
#pragma unroll
                for (int c2 = 0; c2 < 4; ++c2) s[r][c2] += qv[r] * kv[c2];
        }
        const float scale = 0.17677669529663687f;  // 1/sqrt(32)
#pragma unroll
        for (int r = 0; r < 4; ++r)
#pragma unroll
            for (int c2 = 0; c2 < 4; ++c2) S[ti + r][tj + c2] = s[r][c2] * scale;
    }
    __syncthreads();

    // softmax: 4 lanes per row, 16 cols each
    {
        int row = tid >> 2, j0 = (tid & 3) * 16;
        float m = -1e30f;
#pragma unroll
        for (int k = 0; k < 16; ++k) m = fmaxf(m, S[row][j0 + k]);
        m = fmaxf(m, __shfl_xor_sync(0xffffffffu, m, 1));
        m = fmaxf(m, __shfl_xor_sync(0xffffffffu, m, 2));
        float sum = 0.f;
#pragma unroll
        for (int k = 0; k < 16; ++k) {
            float e = __expf(S[row][j0 + k] - m);
            S[row][j0 + k] = e; sum += e;
        }
        sum += __shfl_xor_sync(0xffffffffu, sum, 1);
        sum += __shfl_xor_sync(0xffffffffu, sum, 2);
        if ((tid & 3) == 0) rinv[row] = 1.f / sum;
    }
    __syncthreads();

    // SV: 2 rows x 4 cols per thread
    {
        int r0 = (tid >> 3) * 2, dc = (tid & 7) * 4;
        float a0[4] = {0.f, 0.f, 0.f, 0.f}, a1[4] = {0.f, 0.f, 0.f, 0.f};
#pragma unroll
        for (int j = 0; j < 64; ++j) {
            float s0 = S[r0][j], s1 = S[r0 + 1][j];
            float4 v = *(const float4*)&Vs[j][dc];
            a0[0] += s0 * v.x; a0[1] += s0 * v.y; a0[2] += s0 * v.z; a0[3] += s0 * v.w;
            a1[0] += s1 * v.x; a1[1] += s1 * v.y; a1[2] += s1 * v.z; a1[3] += s1 * v.w;
        }
        float ri0 = rinv[r0], ri1 = rinv[r0 + 1];
        size_t o0 = (size_t)(win * 64 + r0) * 256 + head * 32 + dc;
#pragma unroll
        for (int c2 = 0; c2 < 4; ++c2) {
            oh[o0 + c2]       = __float2half(a0[c2] * ri0);
            oh[o0 + 256 + c2] = __float2half(a1[c2] * ri1);
        }
    }
}

// ---------------- window reverse + residual + LN2 ----------------
__global__ __launch_bounds__(256)
void resid_ln2(const float* __restrict__ x, const float* __restrict__ a,
               const float* __restrict__ g, const float* __restrict__ bb,
               float* __restrict__ yout, __half* __restrict__ zout) {
    extern __shared__ float xs[];  // [256][65]
    int b = blockIdx.x >> 6, h = blockIdx.x & 63;
    int tid = threadIdx.x;
    const float* xp = x + (size_t)b * 1048576 + h * 64;
#pragma unroll
    for (int it = 0; it < 64; ++it) {
        int e = it * 256 + tid;
        int c = e >> 6, w = e & 63;
        xs[c * 65 + w] = xp[(size_t)c * 4096 + w];
    }
    __syncthreads();
    int warp = tid >> 5, lane = tid & 31;
#pragma unroll 1
    for (int t = 0; t < 8; ++t) {
        int w = t * 8 + warp;
        size_t tb = (size_t)src_to_token(b, h, w) * 256;
        float v[8]; float s = 0.f;
#pragma unroll
        for (int k = 0; k < 8; k++) {
            int c = k * 32 + lane;
            v[k] = xs[c * 65 + w] + a[tb + c];
            s += v[k];
        }
#pragma unroll
        for (int o2 = 16; o2; o2 >>= 1) s += __shfl_xor_sync(0xffffffffu, s, o2);
        float mu = s * 0.00390625f;
        float q = 0.f;
#pragma unroll
        for (int k = 0; k < 8; k++) { float d = v[k] - mu; q += d * d; }
#pragma unroll
        for (int o2 = 16; o2; o2 >>= 1) q += __shfl_xor_sync(0xffffffffu, q, o2);
        float rs = rsqrtf(q * 0.00390625f + 1e-6f);
#pragma unroll
        for (int k = 0; k < 8; k++) {
            int c = k * 32 + lane;
            yout[tb + c] = v[k];
            zout[tb + c] = __float2half((v[k] - mu) * rs * g[c] + bb[c]);
        }
    }
}

// ---------------- final: out[b,c,h,w] = y_tok + mlp_tok, smem transpose ----
#define FIN_SMEM (64 * 257 * 4)
__global__ __launch_bounds__(256)
void final_add(const float* __restrict__ y, const float* __restrict__ m,
               float* __restrict__ out) {
    extern __shared__ float ss[];  // [64 tokens][257]
    int b = blockIdx.x >> 6, h = blockIdx.x & 63;
    int tid = threadIdx.x;
    int warp = tid >> 5, lane = tid & 31;
#pragma unroll 1
    for (int t = 0; t < 8; ++t) {
        int w = t * 8 + warp;
        size_t tb = (size_t)src_to_token(b, h, w) * 256;
#pragma unroll
        for (int k = 0; k < 8; k++) {
            int c = k * 32 + lane;
            ss[w * 257 + c] = y[tb + c] + m[tb + c];
        }
    }
    __syncthreads();
    float* op = out + (size_t)b * 1048576 + h * 64;
#pragma unroll
    for (int it = 0; it < 64; ++it) {
        int e = it * 256 + tid;
        int c = e >> 6, w = e & 63;
        op[(size_t)c * 4096 + w] = ss[w * 257 + c];
    }
}

// ---------------- launch ----------------
extern "C" void kernel_launch(void* const* d_in, const int* in_sizes, int n_in,
                              void* d_out, int out_size) {
    const float* x      = (const float*)d_in[0];
    const float* n1g    = (const float*)d_in[1];
    const float* n1b    = (const float*)d_in[2];
    const float* in_w   = (const float*)d_in[3];
    const float* in_b   = (const float*)d_in[4];
    const float* out_w  = (const float*)d_in[5];
    const float* out_b  = (const float*)d_in[6];
    const float* proj_w = (const float*)d_in[7];
    const float* proj_b = (const float*)d_in[8];
    const float* n2g    = (const float*)d_in[9];
    const float* n2b    = (const float*)d_in[10];
    const float* fc1_w  = (const float*)d_in[11];
    const float* fc1_b  = (const float*)d_in[12];
    const float* fc2_w  = (const float*)d_in[13];
    const float* fc2_b  = (const float*)d_in[14];
    float* out = (float*)d_out;

    __half *xn, *qkv, *at, *zb2, *h1, *wh, *wls;
    float *attn2, *yb, *mlp, *bcomb;
    cudaGetSymbolAddress((void**)&xn,    g_xn);
    cudaGetSymbolAddress((void**)&qkv,   g_qkv);
    cudaGetSymbolAddress((void**)&at,    g_at);
    cudaGetSymbolAddress((void**)&attn2, g_attn2);
    cudaGetSymbolAddress((void**)&yb,    g_y);
    cudaGetSymbolAddress((void**)&zb2,   g_z);
    cudaGetSymbolAddress((void**)&h1,    g_h1);
    cudaGetSymbolAddress((void**)&mlp,   g_mlp);
    cudaGetSymbolAddress((void**)&wh,    g_w_h);
    cudaGetSymbolAddress((void**)&wls,   g_w_ls);
    cudaGetSymbolAddress((void**)&bcomb, g_bcomb);

    cudaFuncSetAttribute(mma_gemm<0, false>, cudaFuncAttributeMaxDynamicSharedMemorySize, GEMM_SMEM);
    cudaFuncSetAttribute(mma_gemm<1, false>, cudaFuncAttributeMaxDynamicSharedMemorySize, GEMM_SMEM);
    cudaFuncSetAttribute(mma_gemm<1, true >, cudaFuncAttributeMaxDynamicSharedMemorySize, GEMM_SMEM);
    cudaFuncSetAttribute(ln1_part,  cudaFuncAttributeMaxDynamicSharedMemorySize, LN_SMEM);
    cudaFuncSetAttribute(resid_ln2, cudaFuncAttributeMaxDynamicSharedMemorySize, LN_SMEM);
    cudaFuncSetAttribute(final_add, cudaFuncAttributeMaxDynamicSharedMemorySize, FIN_SMEM);

    // prep: weight split (1 launch) + combined out/proj weight
    cvtw3<<<2816, 256>>>(in_w, fc1_w, fc2_w, wh, wls);
    wcomb<<<256, 256>>>(proj_w, out_w, out_b, proj_b, wh, wls, bcomb);

    ln1_part<<<1024, 256, LN_SMEM>>>(x, n1g, n1b, xn);

    // qkv: [65536,768] = xn @ in_w^T  (fp16 out)
    mma_gemm<1, false><<<dim3(6, 512), 256, GEMM_SMEM>>>(
        xn, wh + OFF_INW, wls + OFF_INW, in_b, nullptr, qkv, 768, 256);

    attn_kernel<<<dim3(1024, 8), 256>>>(qkv, at);

    // combined out_w∘proj_w: [65536,256]
    mma_gemm<0, false><<<dim3(2, 512), 256, GEMM_SMEM>>>(
        at, wh + OFF_CMBW, wls + OFF_CMBW, bcomb, attn2, nullptr, 256, 256);

    resid_ln2<<<1024, 256, LN_SMEM>>>(x, attn2, n2g, n2b, yb, zb2);

    // fc1 + gelu: [65536,1024]
    mma_gemm<1, true><<<dim3(8, 512), 256, GEMM_SMEM>>>(
        zb2, wh + OFF_FC1W, wls + OFF_FC1W, fc1_b, nullptr, h1, 1024, 256);

    // fc2: [65536,256], K=1024
    mma_gemm<0, false><<<dim3(2, 512), 256, GEMM_SMEM>>>(
        h1, wh + OFF_FC2W, wls + OFF_FC2W, fc2_b, mlp, nullptr, 256, 1024);

    final_add<<<1024, 256, FIN_SMEM>>>(yb, mlp, out);
}

// round 15
// speedup vs baseline: 1.6873x; 1.2821x over previous
#include <cuda_runtime.h>
#include <cuda_fp16.h>
#include <cstdint>
#include <cstddef>

#define NTOK 65536  // 16 * 64 * 64 tokens

// ---------------- scratch (no allocations allowed) ----------------
__device__ __half g_xn  [(size_t)NTOK * 256];
__device__ __half g_qkv [(size_t)NTOK * 768];
__device__ __half g_at  [(size_t)NTOK * 256];
__device__ float  g_attn2[(size_t)NTOK * 256];
__device__ float  g_y   [(size_t)NTOK * 256];
__device__ __half g_z   [(size_t)NTOK * 256];
__device__ __half g_h1  [(size_t)NTOK * 1024];
__device__ float  g_mlp [(size_t)NTOK * 256];
// fp16 weights: in_w(196608) comb_w(65536) fc1_w(262144) fc2_w(262144)
__device__ __half g_w   [786432];
__device__ float  g_bcomb[256];

#define OFF_INW  0
#define OFF_CMBW 196608
#define OFF_FC1W 262144
#define OFF_FC2W 524288

// ---------------- small helpers ----------------
__device__ __forceinline__ uint32_t smem_u32(const void* p) {
    uint32_t a;
    asm("{ .reg .u64 t; cvta.to.shared.u64 t, %1; cvt.u32.u64 %0, t; }" : "=r"(a) : "l"(p));
    return a;
}

#define CPA16(dst, src) \
    asm volatile("cp.async.cg.shared.global [%0], [%1], 16;\n" :: "r"(dst), "l"(src))
#define CPA_COMMIT() asm volatile("cp.async.commit_group;\n" ::: "memory")
#define CPA_WAIT1()  asm volatile("cp.async.wait_group 1;\n" ::: "memory")

__device__ __forceinline__ void ldsm4(uint32_t* r, uint32_t addr) {
    asm volatile("ldmatrix.sync.aligned.m8n8.x4.shared.b16 {%0,%1,%2,%3}, [%4];\n"
                 : "=r"(r[0]), "=r"(r[1]), "=r"(r[2]), "=r"(r[3]) : "r"(addr));
}
__device__ __forceinline__ void mma16816(float* c, const uint32_t* a, uint32_t b0, uint32_t b1) {
    asm volatile(
        "mma.sync.aligned.m16n8k16.row.col.f32.f16.f16.f32 "
        "{%0,%1,%2,%3}, {%4,%5,%6,%7}, {%8,%9}, {%0,%1,%2,%3};\n"
        : "+f"(c[0]), "+f"(c[1]), "+f"(c[2]), "+f"(c[3])
        : "r"(a[0]), "r"(a[1]), "r"(a[2]), "r"(a[3]), "r"(b0), "r"(b1));
}

// ---------------- mma.sync plain-fp16 GEMM ----------------
// C[M,N] = A[M,K] @ B[N,K]^T + bias, A and B fp16, fp32 accumulate.
// Block 128x128, 8 warps (2x4), warp tile 64x32, BK=32.
// 3-stage cp.async pipeline, ONE __syncthreads per chunk (load(c+2) writes
// stage (c-1)%3 which the sync proves consumed), 2 CTA/SM enforced.
// smem tile: 128 rows x 80B (64B data + 16B pad) -> ldmatrix conflict-free.
#define ROW_B       80
#define TILE_B      (128 * ROW_B)     // 10240
#define STAGE_B     (2 * TILE_B)      // 20480 (A | B)
#define GEMM_SMEM   (3 * STAGE_B)     // 61440 ; 2 CTAs = 122880

template <int OUTMODE /*0=f32, 1=fp16*/, bool GELU>
__global__ __launch_bounds__(256, 2)
void mma_gemm(const __half* __restrict__ A, const __half* __restrict__ B,
              const float* __restrict__ bias,
              float* __restrict__ Cf, __half* __restrict__ Ch,
              int N, int K) {
    extern __shared__ char smem[];
    const uint32_t sb0 = smem_u32(smem);
    const int tid = threadIdx.x, lane = tid & 31, wid = tid >> 5;
    const int wm = wid >> 2, wn = wid & 3;        // 2 x 4 warp grid
    const int bm = blockIdx.y * 128, bn = blockIdx.x * 128;

    float acc[4][4][4];
#pragma unroll
    for (int i = 0; i < 4; i++)
#pragma unroll
        for (int j = 0; j < 4; j++)
#pragma unroll
            for (int k = 0; k < 4; k++) acc[i][j][k] = 0.f;

    const int nc = K >> 5;  // BK=32 chunks

    auto load_stage = [&](int c, int s) {
        const uint32_t base = sb0 + s * STAGE_B;
        const size_t k0 = (size_t)c << 5;
#pragma unroll
        for (int it = 0; it < 2; ++it) {
            int e = it * 256 + tid;
            int row = e >> 2, ch = e & 3;
            uint32_t d = base + row * ROW_B + ch * 16;
            size_t ga = ((size_t)(bm + row) * K + k0 + ch * 8) * 2;
            size_t gb = ((size_t)(bn + row) * K + k0 + ch * 8) * 2;
            CPA16(d,          (const char*)A + ga);
            CPA16(d + TILE_B, (const char*)B + gb);
        }
        CPA_COMMIT();
    };

    load_stage(0, 0);
    load_stage(1, 1);

    // per-warp ldmatrix base offsets (within a tile)
    const uint32_t a_off = (uint32_t)((wm * 64 + (lane & 15)) * ROW_B + (lane >> 4) * 16);
    const uint32_t b_off = (uint32_t)((wn * 32 + (lane & 7) + ((lane >> 4) << 3)) * ROW_B +
                                      ((lane >> 3) & 1) * 16);

    for (int c = 0; c < nc; ++c) {
        CPA_WAIT1();          // stage c arrived (<=1 group pending)
        __syncthreads();      // all warps done reading stage (c-1)%3
        if (c + 2 < nc) load_stage(c + 2, (c + 2) % 3);

        const uint32_t base = sb0 + (c % 3) * STAGE_B;
        const uint32_t ab = base + a_off;
        const uint32_t bb = base + TILE_B + b_off;
#pragma unroll
        for (int ks = 0; ks < 2; ++ks) {
            uint32_t a[4][4], b[2][4];
#pragma unroll
            for (int mf = 0; mf < 4; ++mf) ldsm4(a[mf], ab + mf * 16 * ROW_B + ks * 32);
#pragma unroll
            for (int nf = 0; nf < 2; ++nf) ldsm4(b[nf], bb + nf * 16 * ROW_B + ks * 32);
#pragma unroll
            for (int mf = 0; mf < 4; ++mf)
#pragma unroll
                for (int nf = 0; nf < 2; ++nf)
#pragma unroll
                    for (int sub = 0; sub < 2; ++sub)
                        mma16816(acc[mf][nf * 2 + sub], a[mf],
                                 b[nf][sub * 2], b[nf][sub * 2 + 1]);
        }
    }

    // epilogue straight from fragments
#pragma unroll
    for (int mf = 0; mf < 4; ++mf) {
#pragma unroll
        for (int nf8 = 0; nf8 < 4; ++nf8) {
            int row = bm + wm * 64 + mf * 16 + (lane >> 2);
            int col = bn + wn * 32 + nf8 * 8 + (lane & 3) * 2;
            float b0 = bias[col], b1 = bias[col + 1];
#pragma unroll
            for (int half_ = 0; half_ < 2; ++half_) {
                int r = row + half_ * 8;
                float v0 = acc[mf][nf8][half_ * 2 + 0] + b0;
                float v1 = acc[mf][nf8][half_ * 2 + 1] + b1;
                if (GELU) { v0 = v0 * normcdff(v0); v1 = v1 * normcdff(v1); }
                size_t o = (size_t)r * N + col;
                if (OUTMODE == 0) {
                    *(float2*)(Cf + o) = make_float2(v0, v1);
                } else {
                    *(__half2*)(Ch + o) = __floats2half2_rn(v0, v1);
                }
            }
        }
    }
}

// ---------------- weight fp32 -> fp16, 3 segments in one launch ----
__global__ void cvtw3(const float* __restrict__ in_w, const float* __restrict__ fc1_w,
                      const float* __restrict__ fc2_w, __half* __restrict__ w) {
    int i = blockIdx.x * 256 + threadIdx.x;  // 0 .. 720895
    const float* src; int dst;
    if (i < 196608)      { src = in_w;  dst = OFF_INW  + i; }
    else if (i < 458752) { src = fc1_w - 196608; dst = OFF_FC1W + (i - 196608); }
    else                 { src = fc2_w - 458752; dst = OFF_FC2W + (i - 458752); }
    w[dst] = __float2half(src[i]);
}

// ---------------- combined out∘proj weight: W = proj_w @ out_w ----------------
__global__ void wcomb(const float* __restrict__ proj_w, const float* __restrict__ out_w,
                      const float* __restrict__ out_b, const float* __restrict__ proj_b,
                      __half* __restrict__ w, float* __restrict__ bcomb) {
    int i = blockIdx.x;       // output row
    int j = threadIdx.x;      // output col (coalesced over out_w)
    float s = 0.f;
    for (int k = 0; k < 256; ++k)
        s += proj_w[i * 256 + k] * out_w[k * 256 + j];
    w[OFF_CMBW + i * 256 + j] = __float2half(s);
    if (j == 0) {
        float b = proj_b[i];
        for (int k = 0; k < 256; ++k) b += proj_w[i * 256 + k] * out_b[k];
        bcomb[i] = b;
    }
}

// (b,h,w) -> token index T in shifted-window order
__device__ __forceinline__ int src_to_token(int b, int h, int w) {
    int hs = (h + 60) & 63, ws = (w + 60) & 63;
    return ((b * 8 + (hs >> 3)) * 8 + (ws >> 3)) * 64 + (hs & 7) * 8 + (ws & 7);
}

// ---------------- LN1 + shift + window partition -> fp16 ----------------
#define LN_SMEM (256 * 65 * 4)
__global__ __launch_bounds__(256)
void ln1_part(const float* __restrict__ x,
              const float* __restrict__ g, const float* __restrict__ bb,
              __half* __restrict__ o) {
    extern __shared__ float xs[];  // [256][65]
    int b = blockIdx.x >> 6, h = blockIdx.x & 63;
    int tid = threadIdx.x;
    const float* xp = x + (size_t)b * 1048576 + h * 64;
#pragma unroll
    for (int it = 0; it < 64; ++it) {
        int e = it * 256 + tid;
        int c = e >> 6, w = e & 63;
        xs[c * 65 + w] = xp[(size_t)c * 4096 + w];
    }
    __syncthreads();
    int warp = tid >> 5, lane = tid & 31;
#pragma unroll 1
    for (int t = 0; t < 8; ++t) {
        int w = t * 8 + warp;
        float v[8]; float s = 0.f;
#pragma unroll
        for (int k = 0; k < 8; k++) { v[k] = xs[(k * 32 + lane) * 65 + w]; s += v[k]; }
#pragma unroll
        for (int o2 = 16; o2; o2 >>= 1) s += __shfl_xor_sync(0xffffffffu, s, o2);
        float mu = s * 0.00390625f;
        float q = 0.f;
#pragma unroll
        for (int k = 0; k < 8; k++) { float d = v[k] - mu; q += d * d; }
#pragma unroll
        for (int o2 = 16; o2; o2 >>= 1) q += __shfl_xor_sync(0xffffffffu, q, o2);
        float rs = rsqrtf(q * 0.00390625f + 1e-6f);
        size_t tb = (size_t)src_to_token(b, h, w) * 256;
#pragma unroll
        for (int k = 0; k < 8; k++) {
            int c = k * 32 + lane;
            o[tb + c] = __float2half((v[k] - mu) * rs * g[c] + bb[c]);
        }
    }
}

// ---------------- attention: one block per (window, head) — fp16 qkv input ----
__global__ __launch_bounds__(256)
void attn_kernel(const __half* __restrict__ qkv, __half* __restrict__ oh) {
    __shared__ __align__(16) float Qs[64][33];
    __shared__ __align__(16) float Ks[64][33];
    __shared__ __align__(16) float Vs[64][36];
    __shared__ float S[64][65];
    __shared__ float rinv[64];
    int win = blockIdx.x, head = blockIdx.y;
    int tid = threadIdx.x;
    size_t base = (size_t)win * 64 * 768 + head * 32;

    // load q/k/v: 64 rows x 4 uint4 (8 halfs) each; convert to f32 smem
    {
        int i = tid >> 2, c8 = tid & 3, d = c8 * 8;
        const __half* rp = qkv + base + (size_t)i * 768;
        uint4 qv = *((const uint4*)rp + c8);
        uint4 kv = *((const uint4*)(rp + 256) + c8);
        uint4 vv = *((const uint4*)(rp + 512) + c8);
        const __half2* qh = (const __half2*)&qv;
        const __half2* kh = (const __half2*)&kv;
        const __half2* vh = (const __half2*)&vv;
#pragma unroll
        for (int t = 0; t < 4; ++t) {
            float2 f;
            f = __half22float2(qh[t]); Qs[i][d + 2*t] = f.x; Qs[i][d + 2*t + 1] = f.y;
            f = __half22float2(kh[t]); Ks[i][d + 2*t] = f.x; Ks[i][d + 2*t + 1] = f.y;
            f = __half22float2(vh[t]); Vs[i][d + 2*t] = f.x; Vs[i][d + 2*t + 1] = f.y;
        }
    }
    __syncthreads();

    // QK^T, 4x4 per thread (16x16 thread grid)
    {
        int ti = (tid >> 4) * 4, tj = (tid & 15) * 4;
        float s[4][4];
#pragma unroll
        for (int r = 0; r < 4; ++r)
#pragma unroll
            for (int c2 = 0; c2 < 4; ++c2) s[r][c2] = 0.f;
#pragma unroll
        for (int d = 0; d < 32; ++d) {
            float qv[4], kv[4];
#pragma unroll
            for (int r = 0; r < 4; ++r) qv[r] = Qs[ti + r][d];
#pragma unroll
            for (int c2 = 0; c2 < 4; ++c2) kv[c2] = Ks[tj + c2][d];
#pragma unroll
            for (int r = 0; r < 4; ++r)
#pragma unroll
                for (int c2 = 0; c2 < 4; ++c2) s[r][c2] += qv[r] * kv[c2];
        }
        const float scale = 0.17677669529663687f;  // 1/sqrt(32)
#pragma unroll
        for (int r = 0; r < 4; ++r)
#pragma unroll
            for (int c2 = 0; c2 < 4; ++c2) S[ti + r][tj + c2] = s[r][c2] * scale;
    }
    __syncthreads();

    // softmax: 4 lanes per row, 16 cols each
    {
        int row = tid >> 2, j0 = (tid & 3) * 16;
        float m = -1e30f;
#pragma unroll
        for (int k = 0; k < 16; ++k) m = fmaxf(m, S[row][j0 + k]);
        m = fmaxf(m, __shfl_xor_sync(0xffffffffu, m, 1));
        m = fmaxf(m, __shfl_xor_sync(0xffffffffu, m, 2));
        float sum = 0.f;
#pragma unroll
        for (int k = 0; k < 16; ++k) {
            float e = __expf(S[row][j0 + k] - m);
            S[row][j0 + k] = e; sum += e;
        }
        sum += __shfl_xor_sync(0xffffffffu, sum, 1);
        sum += __shfl_xor_sync(0xffffffffu, sum, 2);
        if ((tid & 3) == 0) rinv[row] = 1.f / sum;
    }
    __syncthreads();

    // SV: 2 rows x 4 cols per thread
    {
        int r0 = (tid >> 3) * 2, dc = (tid & 7) * 4;
        float a0[4] = {0.f, 0.f, 0.f, 0.f}, a1[4] = {0.f, 0.f, 0.f, 0.f};
#pragma unroll
        for (int j = 0; j < 64; ++j) {
            float s0 = S[r0][j], s1 = S[r0 + 1][j];
            float4 v = *(const float4*)&Vs[j][dc];
            a0[0] += s0 * v.x; a0[1] += s0 * v.y; a0[2] += s0 * v.z; a0[3] += s0 * v.w;
            a1[0] += s1 * v.x; a1[1] += s1 * v.y; a1[2] += s1 * v.z; a1[3] += s1 * v.w;
        }
        float ri0 = rinv[r0], ri1 = rinv[r0 + 1];
        size_t o0 = (size_t)(win * 64 + r0) * 256 + head * 32 + dc;
#pragma unroll
        for (int c2 = 0; c2 < 4; ++c2) {
            oh[o0 + c2]       = __float2half(a0[c2] * ri0);
            oh[o0 + 256 + c2] = __float2half(a1[c2] * ri1);
        }
    }
}

// ---------------- window reverse + residual + LN2 ----------------
__global__ __launch_bounds__(256)
void resid_ln2(const float* __restrict__ x, const float* __restrict__ a,
               const float* __restrict__ g, const float* __restrict__ bb,
               float* __restrict__ yout, __half* __restrict__ zout) {
    extern __shared__ float xs[];  // [256][65]
    int b = blockIdx.x >> 6, h = blockIdx.x & 63;
    int tid = threadIdx.x;
    const float* xp = x + (size_t)b * 1048576 + h * 64;
#pragma unroll
    for (int it = 0; it < 64; ++it) {
        int e = it * 256 + tid;
        int c = e >> 6, w = e & 63;
        xs[c * 65 + w] = xp[(size_t)c * 4096 + w];
    }
    __syncthreads();
    int warp = tid >> 5, lane = tid & 31;
#pragma unroll 1
    for (int t = 0; t < 8; ++t) {
        int w = t * 8 + warp;
        size_t tb = (size_t)src_to_token(b, h, w) * 256;
        float v[8]; float s = 0.f;
#pragma unroll
        for (int k = 0; k < 8; k++) {
            int c = k * 32 + lane;
            v[k] = xs[c * 65 + w] + a[tb + c];
            s += v[k];
        }
#pragma unroll
        for (int o2 = 16; o2; o2 >>= 1) s += __shfl_xor_sync(0xffffffffu, s, o2);
        float mu = s * 0.00390625f;
        float q = 0.f;
#pragma unroll
        for (int k = 0; k < 8; k++) { float d = v[k] - mu; q += d * d; }
#pragma unroll
        for (int o2 = 16; o2; o2 >>= 1) q += __shfl_xor_sync(0xffffffffu, q, o2);
        float rs = rsqrtf(q * 0.00390625f + 1e-6f);
#pragma unroll
        for (int k = 0; k < 8; k++) {
            int c = k * 32 + lane;
            yout[tb + c] = v[k];
            zout[tb + c] = __float2half((v[k] - mu) * rs * g[c] + bb[c]);
        }
    }
}

// ---------------- final: out[b,c,h,w] = y_tok + mlp_tok, smem transpose ----
#define FIN_SMEM (64 * 257 * 4)
__global__ __launch_bounds__(256)
void final_add(const float* __restrict__ y, const float* __restrict__ m,
               float* __restrict__ out) {
    extern __shared__ float ss[];  // [64 tokens][257]
    int b = blockIdx.x >> 6, h = blockIdx.x & 63;
    int tid = threadIdx.x;
    int warp = tid >> 5, lane = tid & 31;
#pragma unroll 1
    for (int t = 0; t < 8; ++t) {
        int w = t * 8 + warp;
        size_t tb = (size_t)src_to_token(b, h, w) * 256;
#pragma unroll
        for (int k = 0; k < 8; k++) {
            int c = k * 32 + lane;
            ss[w * 257 + c] = y[tb + c] + m[tb + c];
        }
    }
    __syncthreads();
    float* op = out + (size_t)b * 1048576 + h * 64;
#pragma unroll
    for (int it = 0; it < 64; ++it) {
        int e = it * 256 + tid;
        int c = e >> 6, w = e & 63;
        op[(size_t)c * 4096 + w] = ss[w * 257 + c];
    }
}

// ---------------- launch ----------------
extern "C" void kernel_launch(void* const* d_in, const int* in_sizes, int n_in,
                              void* d_out, int out_size) {
    const float* x      = (const float*)d_in[0];
    const float* n1g    = (const float*)d_in[1];
    const float* n1b    = (const float*)d_in[2];
    const float* in_w   = (const float*)d_in[3];
    const float* in_b   = (const float*)d_in[4];
    const float* out_w  = (const float*)d_in[5];
    const float* out_b  = (const float*)d_in[6];
    const float* proj_w = (const float*)d_in[7];
    const float* proj_b = (const float*)d_in[8];
    const float* n2g    = (const float*)d_in[9];
    const float* n2b    = (const float*)d_in[10];
    const float* fc1_w  = (const float*)d_in[11];
    const float* fc1_b  = (const float*)d_in[12];
    const float* fc2_w  = (const float*)d_in[13];
    const float* fc2_b  = (const float*)d_in[14];
    float* out = (float*)d_out;

    __half *xn, *qkv, *at, *zb2, *h1, *wp;
    float *attn2, *yb, *mlp, *bcomb;
    cudaGetSymbolAddress((void**)&xn,    g_xn);
    cudaGetSymbolAddress((void**)&qkv,   g_qkv);
    cudaGetSymbolAddress((void**)&at,    g_at);
    cudaGetSymbolAddress((void**)&attn2, g_attn2);
    cudaGetSymbolAddress((void**)&yb,    g_y);
    cudaGetSymbolAddress((void**)&zb2,   g_z);
    cudaGetSymbolAddress((void**)&h1,    g_h1);
    cudaGetSymbolAddress((void**)&mlp,   g_mlp);
    cudaGetSymbolAddress((void**)&wp,    g_w);
    cudaGetSymbolAddress((void**)&bcomb, g_bcomb);

    cudaFuncSetAttribute(mma_gemm<0, false>, cudaFuncAttributeMaxDynamicSharedMemorySize, GEMM_SMEM);
    cudaFuncSetAttribute(mma_gemm<1, false>, cudaFuncAttributeMaxDynamicSharedMemorySize, GEMM_SMEM);
    cudaFuncSetAttribute(mma_gemm<1, true >, cudaFuncAttributeMaxDynamicSharedMemorySize, GEMM_SMEM);
    cudaFuncSetAttribute(ln1_part,  cudaFuncAttributeMaxDynamicSharedMemorySize, LN_SMEM);
    cudaFuncSetAttribute(resid_ln2, cudaFuncAttributeMaxDynamicSharedMemorySize, LN_SMEM);
    cudaFuncSetAttribute(final_add, cudaFuncAttributeMaxDynamicSharedMemorySize, FIN_SMEM);

    // prep: weight conversion (1 launch) + combined out/proj weight
    cvtw3<<<2816, 256>>>(in_w, fc1_w, fc2_w, wp);
    wcomb<<<256, 256>>>(proj_w, out_w, out_b, proj_b, wp, bcomb);

    ln1_part<<<1024, 256, LN_SMEM>>>(x, n1g, n1b, xn);

    // qkv: [65536,768] = xn @ in_w^T  (fp16 out)
    mma_gemm<1, false><<<dim3(6, 512), 256, GEMM_SMEM>>>(
        xn, wp + OFF_INW, in_b, nullptr, qkv, 768, 256);

    attn_kernel<<<dim3(1024, 8), 256>>>(qkv, at);

    // combined out_w∘proj_w: [65536,256]
    mma_gemm<0, false><<<dim3(2, 512), 256, GEMM_SMEM>>>(
        at, wp + OFF_CMBW, bcomb, attn2, nullptr, 256, 256);

    resid_ln2<<<1024, 256, LN_SMEM>>>(x, attn2, n2g, n2b, yb, zb2);

    // fc1 + gelu: [65536,1024]
    mma_gemm<1, true><<<dim3(8, 512), 256, GEMM_SMEM>>>(
        zb2, wp + OFF_FC1W, fc1_b, nullptr, h1, 1024, 256);

    // fc2: [65536,256], K=1024
    mma_gemm<0, false><<<dim3(2, 512), 256, GEMM_SMEM>>>(
        h1, wp + OFF_FC2W, fc2_b, mlp, nullptr, 256, 1024);

    final_add<<<1024, 256, FIN_SMEM>>>(yb, mlp, out);
}

// round 16
// speedup vs baseline: 1.7022x; 1.0088x over previous
#include <cuda_runtime.h>
#include <cuda_fp16.h>
#include <cstdint>
#include <cstddef>

#define NTOK 65536  // 16 * 64 * 64 tokens

// ---------------- scratch (no allocations allowed) ----------------
__device__ __half g_xn  [(size_t)NTOK * 256];
__device__ __half g_qkv [(size_t)NTOK * 768];
__device__ __half g_at  [(size_t)NTOK * 256];
__device__ float  g_attn2[(size_t)NTOK * 256];
__device__ __half g_z   [(size_t)NTOK * 256];
__device__ __half g_h1  [(size_t)NTOK * 1024];
__device__ float  g_mlp [(size_t)NTOK * 256];
// fp16 weights: in_w(196608) comb_w(65536) fc1_w(262144) fc2_w(262144)
__device__ __half g_w   [786432];
__device__ float  g_bcomb[256];

#define OFF_INW  0
#define OFF_CMBW 196608
#define OFF_FC1W 262144
#define OFF_FC2W 524288

// ---------------- small helpers ----------------
__device__ __forceinline__ uint32_t smem_u32(const void* p) {
    uint32_t a;
    asm("{ .reg .u64 t; cvta.to.shared.u64 t, %1; cvt.u32.u64 %0, t; }" : "=r"(a) : "l"(p));
    return a;
}

#define CPA16(dst, src) \
    asm volatile("cp.async.cg.shared.global [%0], [%1], 16;\n" :: "r"(dst), "l"(src))
#define CPA_COMMIT() asm volatile("cp.async.commit_group;\n" ::: "memory")
#define CPA_WAIT1()  asm volatile("cp.async.wait_group 1;\n" ::: "memory")

__device__ __forceinline__ void ldsm4(uint32_t* r, uint32_t addr) {
    asm volatile("ldmatrix.sync.aligned.m8n8.x4.shared.b16 {%0,%1,%2,%3}, [%4];\n"
                 : "=r"(r[0]), "=r"(r[1]), "=r"(r[2]), "=r"(r[3]) : "r"(addr));
}
__device__ __forceinline__ void mma16816(float* c, const uint32_t* a, uint32_t b0, uint32_t b1) {
    asm volatile(
        "mma.sync.aligned.m16n8k16.row.col.f32.f16.f16.f32 "
        "{%0,%1,%2,%3}, {%4,%5,%6,%7}, {%8,%9}, {%0,%1,%2,%3};\n"
        : "+f"(c[0]), "+f"(c[1]), "+f"(c[2]), "+f"(c[3])
        : "r"(a[0]), "r"(a[1]), "r"(a[2]), "r"(a[3]), "r"(b0), "r"(b1));
}

// ---------------- mma.sync plain-fp16 GEMM, BK=64 ----------------
// C[M,N] = A[M,K] @ B[N,K]^T + bias, A and B fp16, fp32 accumulate.
// Block 128x128, 8 warps (2x4), warp tile 64x32, BK=64 (one sync per 64 K).
// 3-stage cp.async pipeline, ONE __syncthreads per chunk, 2 CTA/SM enforced.
// smem tile: 128 rows x 144B (128B data + 16B pad); 144%128=16 -> each 8-row
// ldmatrix phase hits 8 distinct 16B segments: conflict-free.
#define ROW_B       144
#define TILE_B      (128 * ROW_B)     // 18432
#define STAGE_B     (2 * TILE_B)      // 36864 (A | B)
#define GEMM_SMEM   (3 * STAGE_B)     // 110592 ; 2 CTAs = 221184 <= 228KB

template <int OUTMODE /*0=f32, 1=fp16*/, bool GELU>
__global__ __launch_bounds__(256, 2)
void mma_gemm(const __half* __restrict__ A, const __half* __restrict__ B,
              const float* __restrict__ bias,
              float* __restrict__ Cf, __half* __restrict__ Ch,
              int N, int K) {
    extern __shared__ char smem[];
    const uint32_t sb0 = smem_u32(smem);
    const int tid = threadIdx.x, lane = tid & 31, wid = tid >> 5;
    const int wm = wid >> 2, wn = wid & 3;        // 2 x 4 warp grid
    const int bm = blockIdx.y * 128, bn = blockIdx.x * 128;

    float acc[4][4][4];
#pragma unroll
    for (int i = 0; i < 4; i++)
#pragma unroll
        for (int j = 0; j < 4; j++)
#pragma unroll
            for (int k = 0; k < 4; k++) acc[i][j][k] = 0.f;

    const int nc = K >> 6;  // BK=64 chunks

    auto load_stage = [&](int c, int s) {
        const uint32_t base = sb0 + s * STAGE_B;
        const size_t k0 = (size_t)c << 6;
#pragma unroll
        for (int it = 0; it < 4; ++it) {
            int e = it * 256 + tid;
            int row = e >> 3, ch = e & 7;
            uint32_t d = base + row * ROW_B + ch * 16;
            size_t ga = ((size_t)(bm + row) * K + k0 + ch * 8) * 2;
            size_t gb = ((size_t)(bn + row) * K + k0 + ch * 8) * 2;
            CPA16(d,          (const char*)A + ga);
            CPA16(d + TILE_B, (const char*)B + gb);
        }
        CPA_COMMIT();
    };

    load_stage(0, 0);
    load_stage(1, 1);

    // per-warp ldmatrix base offsets (within a tile)
    const uint32_t a_off = (uint32_t)((wm * 64 + (lane & 15)) * ROW_B + (lane >> 4) * 16);
    const uint32_t b_off = (uint32_t)((wn * 32 + (lane & 7) + ((lane >> 4) << 3)) * ROW_B +
                                      ((lane >> 3) & 1) * 16);

    for (int c = 0; c < nc; ++c) {
        CPA_WAIT1();          // stage c arrived (<=1 group pending)
        __syncthreads();      // all warps done reading stage (c-1)%3
        if (c + 2 < nc) load_stage(c + 2, (c + 2) % 3);

        const uint32_t base = sb0 + (c % 3) * STAGE_B;
        const uint32_t ab = base + a_off;
        const uint32_t bb = base + TILE_B + b_off;
#pragma unroll
        for (int ks = 0; ks < 4; ++ks) {
            uint32_t a[4][4], b[2][4];
#pragma unroll
            for (int mf = 0; mf < 4; ++mf) ldsm4(a[mf], ab + mf * 16 * ROW_B + ks * 32);
#pragma unroll
            for (int nf = 0; nf < 2; ++nf) ldsm4(b[nf], bb + nf * 16 * ROW_B + ks * 32);
#pragma unroll
            for (int mf = 0; mf < 4; ++mf)
#pragma unroll
                for (int nf = 0; nf < 2; ++nf)
#pragma unroll
                    for (int sub = 0; sub < 2; ++sub)
                        mma16816(acc[mf][nf * 2 + sub], a[mf],
                                 b[nf][sub * 2], b[nf][sub * 2 + 1]);
        }
    }

    // epilogue straight from fragments
#pragma unroll
    for (int mf = 0; mf < 4; ++mf) {
#pragma unroll
        for (int nf8 = 0; nf8 < 4; ++nf8) {
            int row = bm + wm * 64 + mf * 16 + (lane >> 2);
            int col = bn + wn * 32 + nf8 * 8 + (lane & 3) * 2;
            float b0 = bias[col], b1 = bias[col + 1];
#pragma unroll
            for (int half_ = 0; half_ < 2; ++half_) {
                int r = row + half_ * 8;
                float v0 = acc[mf][nf8][half_ * 2 + 0] + b0;
                float v1 = acc[mf][nf8][half_ * 2 + 1] + b1;
                if (GELU) { v0 = v0 * normcdff(v0); v1 = v1 * normcdff(v1); }
                size_t o = (size_t)r * N + col;
                if (OUTMODE == 0) {
                    *(float2*)(Cf + o) = make_float2(v0, v1);
                } else {
                    *(__half2*)(Ch + o) = __floats2half2_rn(v0, v1);
                }
            }
        }
    }
}

// ---------------- weight fp32 -> fp16, 3 segments in one launch ----
__global__ void cvtw3(const float* __restrict__ in_w, const float* __restrict__ fc1_w,
                      const float* __restrict__ fc2_w, __half* __restrict__ w) {
    int i = blockIdx.x * 256 + threadIdx.x;  // 0 .. 720895
    const float* src; int dst;
    if (i < 196608)      { src = in_w;  dst = OFF_INW  + i; }
    else if (i < 458752) { src = fc1_w - 196608; dst = OFF_FC1W + (i - 196608); }
    else                 { src = fc2_w - 458752; dst = OFF_FC2W + (i - 458752); }
    w[dst] = __float2half(src[i]);
}

// ---------------- combined out∘proj weight: W = proj_w @ out_w ----------------
__global__ void wcomb(const float* __restrict__ proj_w, const float* __restrict__ out_w,
                      const float* __restrict__ out_b, const float* __restrict__ proj_b,
                      __half* __restrict__ w, float* __restrict__ bcomb) {
    int i = blockIdx.x;       // output row
    int j = threadIdx.x;      // output col (coalesced over out_w)
    float s = 0.f;
    for (int k = 0; k < 256; ++k)
        s += proj_w[i * 256 + k] * out_w[k * 256 + j];
    w[OFF_CMBW + i * 256 + j] = __float2half(s);
    if (j == 0) {
        float b = proj_b[i];
        for (int k = 0; k < 256; ++k) b += proj_w[i * 256 + k] * out_b[k];
        bcomb[i] = b;
    }
}

// (b,h,w) -> token index T in shifted-window order
__device__ __forceinline__ int src_to_token(int b, int h, int w) {
    int hs = (h + 60) & 63, ws = (w + 60) & 63;
    return ((b * 8 + (hs >> 3)) * 8 + (ws >> 3)) * 64 + (hs & 7) * 8 + (ws & 7);
}

// ---------------- LN1 + shift + window partition -> fp16 ----------------
#define LN_SMEM (256 * 65 * 4)
__global__ __launch_bounds__(256)
void ln1_part(const float* __restrict__ x,
              const float* __restrict__ g, const float* __restrict__ bb,
              __half* __restrict__ o) {
    extern __shared__ float xs[];  // [256][65]
    int b = blockIdx.x >> 6, h = blockIdx.x & 63;
    int tid = threadIdx.x;
    const float* xp = x + (size_t)b * 1048576 + h * 64;
#pragma unroll
    for (int it = 0; it < 64; ++it) {
        int e = it * 256 + tid;
        int c = e >> 6, w = e & 63;
        xs[c * 65 + w] = xp[(size_t)c * 4096 + w];
    }
    __syncthreads();
    int warp = tid >> 5, lane = tid & 31;
#pragma unroll 1
    for (int t = 0; t < 8; ++t) {
        int w = t * 8 + warp;
        float v[8]; float s = 0.f;
#pragma unroll
        for (int k = 0; k < 8; k++) { v[k] = xs[(k * 32 + lane) * 65 + w]; s += v[k]; }
#pragma unroll
        for (int o2 = 16; o2; o2 >>= 1) s += __shfl_xor_sync(0xffffffffu, s, o2);
        float mu = s * 0.00390625f;
        float q = 0.f;
#pragma unroll
        for (int k = 0; k < 8; k++) { float d = v[k] - mu; q += d * d; }
#pragma unroll
        for (int o2 = 16; o2; o2 >>= 1) q += __shfl_xor_sync(0xffffffffu, q, o2);
        float rs = rsqrtf(q * 0.00390625f + 1e-6f);
        size_t tb = (size_t)src_to_token(b, h, w) * 256;
#pragma unroll
        for (int k = 0; k < 8; k++) {
            int c = k * 32 + lane;
            o[tb + c] = __float2half((v[k] - mu) * rs * g[c] + bb[c]);
        }
    }
}

// ---------------- attention: one block per (window, head) — fp16 qkv input ----
__global__ __launch_bounds__(256)
void attn_kernel(const __half* __restrict__ qkv, __half* __restrict__ oh) {
    __shared__ __align__(16) float Qs[64][33];
    __shared__ __align__(16) float Ks[64][33];
    __shared__ __align__(16) float Vs[64][36];
    __shared__ float S[64][65];
    __shared__ float rinv[64];
    int win = blockIdx.x, head = blockIdx.y;
    int tid = threadIdx.x;
    size_t base = (size_t)win * 64 * 768 + head * 32;

    // load q/k/v: 64 rows x 4 uint4 (8 halfs) each; convert to f32 smem
    {
        int i = tid >> 2, c8 = tid & 3, d = c8 * 8;
        const __half* rp = qkv + base + (size_t)i * 768;
        uint4 qv = *((const uint4*)rp + c8);
        uint4 kv = *((const uint4*)(rp + 256) + c8);
        uint4 vv = *((const uint4*)(rp + 512) + c8);
        const __half2* qh = (const __half2*)&qv;
        const __half2* kh = (const __half2*)&kv;
        const __half2* vh = (const __half2*)&vv;
#pragma unroll
        for (int t = 0; t < 4; ++t) {
            float2 f;
            f = __half22float2(qh[t]); Qs[i][d + 2*t] = f.x; Qs[i][d + 2*t + 1] = f.y;
            f = __half22float2(kh[t]); Ks[i][d + 2*t] = f.x; Ks[i][d + 2*t + 1] = f.y;
            f = __half22float2(vh[t]); Vs[i][d + 2*t] = f.x; Vs[i][d + 2*t + 1] = f.y;
        }
    }
    __syncthreads();

    // QK^T, 4x4 per thread (16x16 thread grid)
    {
        int ti = (tid >> 4) * 4, tj = (tid & 15) * 4;
        float s[4][4];
#pragma unroll
        for (int r = 0; r < 4; ++r)
#pragma unroll
            for (int c2 = 0; c2 < 4; ++c2) s[r][c2] = 0.f;
#pragma unroll
        for (int d = 0; d < 32; ++d) {
            float qv[4], kv[4];
#pragma unroll
            for (int r = 0; r < 4; ++r) qv[r] = Qs[ti + r][d];
#pragma unroll
            for (int c2 = 0; c2 < 4; ++c2) kv[c2] = Ks[tj + c2][d];
#pragma unroll
            for (int r = 0; r < 4; ++r)
#pragma unroll
                for (int c2 = 0; c2 < 4; ++c2) s[r][c2] += qv[r] * kv[c2];
        }
        const float scale = 0.17677669529663687f;  // 1/sqrt(32)
#pragma unroll
        for (int r = 0; r < 4; ++r)
#pragma unroll
            for (int c2 = 0; c2 < 4; ++c2) S[ti + r][tj + c2] = s[r][c2] * scale;
    }
    __syncthreads();

    // softmax: 4 lanes per row, 16 cols each
    {
        int row = tid >> 2, j0 = (tid & 3) * 16;
        float m = -1e30f;
#pragma unroll
        for (int k = 0; k < 16; ++k) m = fmaxf(m, S[row][j0 + k]);
        m = fmaxf(m, __shfl_xor_sync(0xffffffffu, m, 1));
        m = fmaxf(m, __shfl_xor_sync(0xffffffffu, m, 2));
        float sum = 0.f;
#pragma unroll
        for (int k = 0; k < 16; ++k) {
            float e = __expf(S[row][j0 + k] - m);
            S[row][j0 + k] = e; sum += e;
        }
        sum += __shfl_xor_sync(0xffffffffu, sum, 1);
        sum += __shfl_xor_sync(0xffffffffu, sum, 2);
        if ((tid & 3) == 0) rinv[row] = 1.f / sum;
    }
    __syncthreads();

    // SV: 2 rows x 4 cols per thread
    {
        int r0 = (tid >> 3) * 2, dc = (tid & 7) * 4;
        float a0[4] = {0.f, 0.f, 0.f, 0.f}, a1[4] = {0.f, 0.f, 0.f, 0.f};
#pragma unroll
        for (int j = 0; j < 64; ++j) {
            float s0 = S[r0][j], s1 = S[r0 + 1][j];
            float4 v = *(const float4*)&Vs[j][dc];
            a0[0] += s0 * v.x; a0[1] += s0 * v.y; a0[2] += s0 * v.z; a0[3] += s0 * v.w;
            a1[0] += s1 * v.x; a1[1] += s1 * v.y; a1[2] += s1 * v.z; a1[3] += s1 * v.w;
        }
        float ri0 = rinv[r0], ri1 = rinv[r0 + 1];
        size_t o0 = (size_t)(win * 64 + r0) * 256 + head * 32 + dc;
#pragma unroll
        for (int c2 = 0; c2 < 4; ++c2) {
            oh[o0 + c2]       = __float2half(a0[c2] * ri0);
            oh[o0 + 256 + c2] = __float2half(a1[c2] * ri1);
        }
    }
}

// ---------------- window reverse + residual + LN2 (no y write) ----------------
__global__ __launch_bounds__(256)
void resid_ln2(const float* __restrict__ x, const float* __restrict__ a,
               const float* __restrict__ g, const float* __restrict__ bb,
               __half* __restrict__ zout) {
    extern __shared__ float xs[];  // [256][65]
    int b = blockIdx.x >> 6, h = blockIdx.x & 63;
    int tid = threadIdx.x;
    const float* xp = x + (size_t)b * 1048576 + h * 64;
#pragma unroll
    for (int it = 0; it < 64; ++it) {
        int e = it * 256 + tid;
        int c = e >> 6, w = e & 63;
        xs[c * 65 + w] = xp[(size_t)c * 4096 + w];
    }
    __syncthreads();
    int warp = tid >> 5, lane = tid & 31;
#pragma unroll 1
    for (int t = 0; t < 8; ++t) {
        int w = t * 8 + warp;
        size_t tb = (size_t)src_to_token(b, h, w) * 256;
        float v[8]; float s = 0.f;
#pragma unroll
        for (int k = 0; k < 8; k++) {
            int c = k * 32 + lane;
            v[k] = xs[c * 65 + w] + a[tb + c];
            s += v[k];
        }
#pragma unroll
        for (int o2 = 16; o2; o2 >>= 1) s += __shfl_xor_sync(0xffffffffu, s, o2);
        float mu = s * 0.00390625f;
        float q = 0.f;
#pragma unroll
        for (int k = 0; k < 8; k++) { float d = v[k] - mu; q += d * d; }
#pragma unroll
        for (int o2 = 16; o2; o2 >>= 1) q += __shfl_xor_sync(0xffffffffu, q, o2);
        float rs = rsqrtf(q * 0.00390625f + 1e-6f);
#pragma unroll
        for (int k = 0; k < 8; k++) {
            int c = k * 32 + lane;
            zout[tb + c] = __float2half((v[k] - mu) * rs * g[c] + bb[c]);
        }
    }
}

// ---------------- final: out = x + attn2 + mlp (x read native NCHW) ----------
#define FIN_SMEM (64 * 257 * 4)
__global__ __launch_bounds__(256)
void final_add(const float* __restrict__ x, const float* __restrict__ a,
               const float* __restrict__ m, float* __restrict__ out) {
    extern __shared__ float ss[];  // [64 tokens][257]
    int b = blockIdx.x >> 6, h = blockIdx.x & 63;
    int tid = threadIdx.x;
    int warp = tid >> 5, lane = tid & 31;
#pragma unroll 1
    for (int t = 0; t < 8; ++t) {
        int w = t * 8 + warp;
        size_t tb = (size_t)src_to_token(b, h, w) * 256;
#pragma unroll
        for (int k = 0; k < 8; k++) {
            int c = k * 32 + lane;
            ss[w * 257 + c] = a[tb + c] + m[tb + c];
        }
    }
    __syncthreads();
    const float* xp = x + (size_t)b * 1048576 + h * 64;
    float* op = out + (size_t)b * 1048576 + h * 64;
#pragma unroll
    for (int it = 0; it < 64; ++it) {
        int e = it * 256 + tid;
        int c = e >> 6, w = e & 63;
        op[(size_t)c * 4096 + w] = xp[(size_t)c * 4096 + w] + ss[w * 257 + c];
    }
}

// ---------------- launch ----------------
extern "C" void kernel_launch(void* const* d_in, const int* in_sizes, int n_in,
                              void* d_out, int out_size) {
    const float* x      = (const float*)d_in[0];
    const float* n1g    = (const float*)d_in[1];
    const float* n1b    = (const float*)d_in[2];
    const float* in_w   = (const float*)d_in[3];
    const float* in_b   = (const float*)d_in[4];
    const float* out_w  = (const float*)d_in[5];
    const float* out_b  = (const float*)d_in[6];
    const float* proj_w = (const float*)d_in[7];
    const float* proj_b = (const float*)d_in[8];
    const float* n2g    = (const float*)d_in[9];
    const float* n2b    = (const float*)d_in[10];
    const float* fc1_w  = (const float*)d_in[11];
    const float* fc1_b  = (const float*)d_in[12];
    const float* fc2_w  = (const float*)d_in[13];
    const float* fc2_b  = (const float*)d_in[14];
    float* out = (float*)d_out;

    __half *xn, *qkv, *at, *zb2, *h1, *wp;
    float *attn2, *mlp, *bcomb;
    cudaGetSymbolAddress((void**)&xn,    g_xn);
    cudaGetSymbolAddress((void**)&qkv,   g_qkv);
    cudaGetSymbolAddress((void**)&at,    g_at);
    cudaGetSymbolAddress((void**)&attn2, g_attn2);
    cudaGetSymbolAddress((void**)&zb2,   g_z);
    cudaGetSymbolAddress((void**)&h1,    g_h1);
    cudaGetSymbolAddress((void**)&mlp,   g_mlp);
    cudaGetSymbolAddress((void**)&wp,    g_w);
    cudaGetSymbolAddress((void**)&bcomb, g_bcomb);

    cudaFuncSetAttribute(mma_gemm<0, false>, cudaFuncAttributeMaxDynamicSharedMemorySize, GEMM_SMEM);
    cudaFuncSetAttribute(mma_gemm<1, false>, cudaFuncAttributeMaxDynamicSharedMemorySize, GEMM_SMEM);
    cudaFuncSetAttribute(mma_gemm<1, true >, cudaFuncAttributeMaxDynamicSharedMemorySize, GEMM_SMEM);
    cudaFuncSetAttribute(ln1_part,  cudaFuncAttributeMaxDynamicSharedMemorySize, LN_SMEM);
    cudaFuncSetAttribute(resid_ln2, cudaFuncAttributeMaxDynamicSharedMemorySize, LN_SMEM);
    cudaFuncSetAttribute(final_add, cudaFuncAttributeMaxDynamicSharedMemorySize, FIN_SMEM);

    // prep: weight conversion (1 launch) + combined out/proj weight
    cvtw3<<<2816, 256>>>(in_w, fc1_w, fc2_w, wp);
    wcomb<<<256, 256>>>(proj_w, out_w, out_b, proj_b, wp, bcomb);

    ln1_part<<<1024, 256, LN_SMEM>>>(x, n1g, n1b, xn);

    // qkv: [65536,768] = xn @ in_w^T  (fp16 out)
    mma_gemm<1, false><<<dim3(6, 512), 256, GEMM_SMEM>>>(
        xn, wp + OFF_INW, in_b, nullptr, qkv, 768, 256);

    attn_kernel<<<dim3(1024, 8), 256>>>(qkv, at);

    // combined out_w∘proj_w: [65536,256]
    mma_gemm<0, false><<<dim3(2, 512), 256, GEMM_SMEM>>>(
        at, wp + OFF_CMBW, bcomb, attn2, nullptr, 256, 256);

    resid_ln2<<<1024, 256, LN_SMEM>>>(x, attn2, n2g, n2b, zb2);

    // fc1 + gelu: [65536,1024]
    mma_gemm<1, true><<<dim3(8, 512), 256, GEMM_SMEM>>>(
        zb2, wp + OFF_FC1W, fc1_b, nullptr, h1, 1024, 256);

    // fc2: [65536,256], K=1024
    mma_gemm<0, false><<<dim3(2, 512), 256, GEMM_SMEM>>>(
        h1, wp + OFF_FC2W, fc2_b, mlp, nullptr, 256, 1024);

    final_add<<<1024, 256, FIN_SMEM>>>(x, attn2, mlp, out);
}

// round 17
// speedup vs baseline: 1.7229x; 1.0122x over previous
#include <cuda_runtime.h>
#include <cuda_fp16.h>
#include <cstdint>
#include <cstddef>

#define NTOK 65536  // 16 * 64 * 64 tokens

// ---------------- scratch (no allocations allowed) ----------------
__device__ __half g_xn  [(size_t)NTOK * 256];
__device__ __half g_qkv [(size_t)NTOK * 768];
__device__ __half g_at  [(size_t)NTOK * 256];
__device__ __half g_attn2[(size_t)NTOK * 256];
__device__ __half g_z   [(size_t)NTOK * 256];
__device__ __half g_h1  [(size_t)NTOK * 1024];
__device__ __half g_mlp [(size_t)NTOK * 256];
// fp16 weights: in_w(196608) comb_w(65536) fc1_w(262144) fc2_w(262144)
__device__ __half g_w   [786432];
__device__ float  g_bcomb[256];

#define OFF_INW  0
#define OFF_CMBW 196608
#define OFF_FC1W 262144
#define OFF_FC2W 524288

// ---------------- small helpers ----------------
__device__ __forceinline__ uint32_t smem_u32(const void* p) {
    uint32_t a;
    asm("{ .reg .u64 t; cvta.to.shared.u64 t, %1; cvt.u32.u64 %0, t; }" : "=r"(a) : "l"(p));
    return a;
}

#define CPA16(dst, src) \
    asm volatile("cp.async.cg.shared.global [%0], [%1], 16;\n" :: "r"(dst), "l"(src))
#define CPA_COMMIT() asm volatile("cp.async.commit_group;\n" ::: "memory")
#define CPA_WAIT1()  asm volatile("cp.async.wait_group 1;\n" ::: "memory")

__device__ __forceinline__ void ldsm4(uint32_t* r, uint32_t addr) {
    asm volatile("ldmatrix.sync.aligned.m8n8.x4.shared.b16 {%0,%1,%2,%3}, [%4];\n"
                 : "=r"(r[0]), "=r"(r[1]), "=r"(r[2]), "=r"(r[3]) : "r"(addr));
}
__device__ __forceinline__ void mma16816(float* c, const uint32_t* a, uint32_t b0, uint32_t b1) {
    asm volatile(
        "mma.sync.aligned.m16n8k16.row.col.f32.f16.f16.f32 "
        "{%0,%1,%2,%3}, {%4,%5,%6,%7}, {%8,%9}, {%0,%1,%2,%3};\n"
        : "+f"(c[0]), "+f"(c[1]), "+f"(c[2]), "+f"(c[3])
        : "r"(a[0]), "r"(a[1]), "r"(a[2]), "r"(a[3]), "r"(b0), "r"(b1));
}

// ---------------- mma.sync plain-fp16 GEMM, BK=64 ----------------
// C[M,N] = A[M,K] @ B[N,K]^T + bias, A and B fp16, fp32 accumulate.
// Block 128x128, 8 warps (2x4), warp tile 64x32, BK=64 (one sync per 64 K).
// 3-stage cp.async pipeline, ONE __syncthreads per chunk, 2 CTA/SM enforced.
// smem tile: 128 rows x 144B (128B data + 16B pad): conflict-free ldmatrix.
#define ROW_B       144
#define TILE_B      (128 * ROW_B)     // 18432
#define STAGE_B     (2 * TILE_B)      // 36864 (A | B)
#define GEMM_SMEM   (3 * STAGE_B)     // 110592 ; 2 CTAs = 221184 <= 228KB

template <int OUTMODE /*0=f32, 1=fp16*/, bool GELU>
__global__ __launch_bounds__(256, 2)
void mma_gemm(const __half* __restrict__ A, const __half* __restrict__ B,
              const float* __restrict__ bias,
              float* __restrict__ Cf, __half* __restrict__ Ch,
              int N, int K) {
    extern __shared__ char smem[];
    const uint32_t sb0 = smem_u32(smem);
    const int tid = threadIdx.x, lane = tid & 31, wid = tid >> 5;
    const int wm = wid >> 2, wn = wid & 3;        // 2 x 4 warp grid
    const int bm = blockIdx.y * 128, bn = blockIdx.x * 128;

    float acc[4][4][4];
#pragma unroll
    for (int i = 0; i < 4; i++)
#pragma unroll
        for (int j = 0; j < 4; j++)
#pragma unroll
            for (int k = 0; k < 4; k++) acc[i][j][k] = 0.f;

    const int nc = K >> 6;  // BK=64 chunks

    auto load_stage = [&](int c, int s) {
        const uint32_t base = sb0 + s * STAGE_B;
        const size_t k0 = (size_t)c << 6;
#pragma unroll
        for (int it = 0; it < 4; ++it) {
            int e = it * 256 + tid;
            int row = e >> 3, ch = e & 7;
            uint32_t d = base + row * ROW_B + ch * 16;
            size_t ga = ((size_t)(bm + row) * K + k0 + ch * 8) * 2;
            size_t gb = ((size_t)(bn + row) * K + k0 + ch * 8) * 2;
            CPA16(d,          (const char*)A + ga);
            CPA16(d + TILE_B, (const char*)B + gb);
        }
        CPA_COMMIT();
    };

    load_stage(0, 0);
    load_stage(1, 1);

    // per-warp ldmatrix base offsets (within a tile)
    const uint32_t a_off = (uint32_t)((wm * 64 + (lane & 15)) * ROW_B + (lane >> 4) * 16);
    const uint32_t b_off = (uint32_t)((wn * 32 + (lane & 7) + ((lane >> 4) << 3)) * ROW_B +
                                      ((lane >> 3) & 1) * 16);

    for (int c = 0; c < nc; ++c) {
        CPA_WAIT1();          // stage c arrived (<=1 group pending)
        __syncthreads();      // all warps done reading stage (c-1)%3
        if (c + 2 < nc) load_stage(c + 2, (c + 2) % 3);

        const uint32_t base = sb0 + (c % 3) * STAGE_B;
        const uint32_t ab = base + a_off;
        const uint32_t bb = base + TILE_B + b_off;
#pragma unroll
        for (int ks = 0; ks < 4; ++ks) {
            uint32_t a[4][4], b[2][4];
#pragma unroll
            for (int mf = 0; mf < 4; ++mf) ldsm4(a[mf], ab + mf * 16 * ROW_B + ks * 32);
#pragma unroll
            for (int nf = 0; nf < 2; ++nf) ldsm4(b[nf], bb + nf * 16 * ROW_B + ks * 32);
#pragma unroll
            for (int mf = 0; mf < 4; ++mf)
#pragma unroll
                for (int nf = 0; nf < 2; ++nf)
#pragma unroll
                    for (int sub = 0; sub < 2; ++sub)
                        mma16816(acc[mf][nf * 2 + sub], a[mf],
                                 b[nf][sub * 2], b[nf][sub * 2 + 1]);
        }
    }

    // epilogue straight from fragments
#pragma unroll
    for (int mf = 0; mf < 4; ++mf) {
#pragma unroll
        for (int nf8 = 0; nf8 < 4; ++nf8) {
            int row = bm + wm * 64 + mf * 16 + (lane >> 2);
            int col = bn + wn * 32 + nf8 * 8 + (lane & 3) * 2;
            float b0 = bias[col], b1 = bias[col + 1];
#pragma unroll
            for (int half_ = 0; half_ < 2; ++half_) {
                int r = row + half_ * 8;
                float v0 = acc[mf][nf8][half_ * 2 + 0] + b0;
                float v1 = acc[mf][nf8][half_ * 2 + 1] + b1;
                if (GELU) { v0 = v0 * normcdff(v0); v1 = v1 * normcdff(v1); }
                size_t o = (size_t)r * N + col;
                if (OUTMODE == 0) {
                    *(float2*)(Cf + o) = make_float2(v0, v1);
                } else {
                    *(__half2*)(Ch + o) = __floats2half2_rn(v0, v1);
                }
            }
        }
    }
}

// ---------------- weight fp32 -> fp16, 3 segments in one launch ----
__global__ void cvtw3(const float* __restrict__ in_w, const float* __restrict__ fc1_w,
                      const float* __restrict__ fc2_w, __half* __restrict__ w) {
    int i = blockIdx.x * 256 + threadIdx.x;  // 0 .. 720895
    const float* src; int dst;
    if (i < 196608)      { src = in_w;  dst = OFF_INW  + i; }
    else if (i < 458752) { src = fc1_w - 196608; dst = OFF_FC1W + (i - 196608); }
    else                 { src = fc2_w - 458752; dst = OFF_FC2W + (i - 458752); }
    w[dst] = __float2half(src[i]);
}

// ---------------- combined out∘proj weight: W = proj_w @ out_w ----------------
__global__ void wcomb(const float* __restrict__ proj_w, const float* __restrict__ out_w,
                      const float* __restrict__ out_b, const float* __restrict__ proj_b,
                      __half* __restrict__ w, float* __restrict__ bcomb) {
    int i = blockIdx.x;       // output row
    int j = threadIdx.x;      // output col (coalesced over out_w)
    float s = 0.f;
    for (int k = 0; k < 256; ++k)
        s += proj_w[i * 256 + k] * out_w[k * 256 + j];
    w[OFF_CMBW + i * 256 + j] = __float2half(s);
    if (j == 0) {
        float b = proj_b[i];
        for (int k = 0; k < 256; ++k) b += proj_w[i * 256 + k] * out_b[k];
        bcomb[i] = b;
    }
}

// (b,h,w) -> token index T in shifted-window order
__device__ __forceinline__ int src_to_token(int b, int h, int w) {
    int hs = (h + 60) & 63, ws = (w + 60) & 63;
    return ((b * 8 + (hs >> 3)) * 8 + (ws >> 3)) * 64 + (hs & 7) * 8 + (ws & 7);
}

// ---------------- LN1 + shift + window partition -> fp16 ----------------
#define LN_SMEM (256 * 65 * 4)
__global__ __launch_bounds__(256)
void ln1_part(const float* __restrict__ x,
              const float* __restrict__ g, const float* __restrict__ bb,
              __half* __restrict__ o) {
    extern __shared__ float xs[];  // [256][65]
    int b = blockIdx.x >> 6, h = blockIdx.x & 63;
    int tid = threadIdx.x;
    const float* xp = x + (size_t)b * 1048576 + h * 64;
#pragma unroll
    for (int it = 0; it < 64; ++it) {
        int e = it * 256 + tid;
        int c = e >> 6, w = e & 63;
        xs[c * 65 + w] = xp[(size_t)c * 4096 + w];
    }
    __syncthreads();
    int warp = tid >> 5, lane = tid & 31;
#pragma unroll 1
    for (int t = 0; t < 8; ++t) {
        int w = t * 8 + warp;
        float v[8]; float s = 0.f;
#pragma unroll
        for (int k = 0; k < 8; k++) { v[k] = xs[(k * 32 + lane) * 65 + w]; s += v[k]; }
#pragma unroll
        for (int o2 = 16; o2; o2 >>= 1) s += __shfl_xor_sync(0xffffffffu, s, o2);
        float mu = s * 0.00390625f;
        float q = 0.f;
#pragma unroll
        for (int k = 0; k < 8; k++) { float d = v[k] - mu; q += d * d; }
#pragma unroll
        for (int o2 = 16; o2; o2 >>= 1) q += __shfl_xor_sync(0xffffffffu, q, o2);
        float rs = rsqrtf(q * 0.00390625f + 1e-6f);
        size_t tb = (size_t)src_to_token(b, h, w) * 256;
#pragma unroll
        for (int k = 0; k < 8; k++) {
            int c = k * 32 + lane;
            o[tb + c] = __float2half((v[k] - mu) * rs * g[c] + bb[c]);
        }
    }
}

// ---------------- attention: fp16-resident smem (half the LDS traffic) -------
// Q/K/V kept fp16 (72B rows; 18*tx mod 32 covers 16 distinct banks).
// QK^T: half2 loads + fp32 FMA. Softmax probs stored fp16. SV: fp16 S and V.
__global__ __launch_bounds__(256)
void attn_kernel(const __half* __restrict__ qkv, __half* __restrict__ oh) {
    __shared__ __align__(16) __half Qh[64][36];   // 72B row
    __shared__ __align__(16) __half Kh[64][36];
    __shared__ __align__(16) __half Vh[64][36];
    __shared__ __align__(16) float  S[64][65];
    __shared__ __align__(16) __half Sh[64][66];   // 132B row
    __shared__ float rinv[64];
    int win = blockIdx.x, head = blockIdx.y;
    int tid = threadIdx.x;
    size_t base = (size_t)win * 64 * 768 + head * 32;

    // load q/k/v: 64 rows x 4 uint4 (8 halves each); store fp16 (4x u32 stores)
    {
        int i = tid >> 2, c8 = tid & 3, d = c8 * 8;
        const __half* rp = qkv + base + (size_t)i * 768;
        uint4 qv = *((const uint4*)rp + c8);
        uint4 kv = *((const uint4*)(rp + 256) + c8);
        uint4 vv = *((const uint4*)(rp + 512) + c8);
        *(uint32_t*)&Qh[i][d + 0] = qv.x; *(uint32_t*)&Qh[i][d + 2] = qv.y;
        *(uint32_t*)&Qh[i][d + 4] = qv.z; *(uint32_t*)&Qh[i][d + 6] = qv.w;
        *(uint32_t*)&Kh[i][d + 0] = kv.x; *(uint32_t*)&Kh[i][d + 2] = kv.y;
        *(uint32_t*)&Kh[i][d + 4] = kv.z; *(uint32_t*)&Kh[i][d + 6] = kv.w;
        *(uint32_t*)&Vh[i][d + 0] = vv.x; *(uint32_t*)&Vh[i][d + 2] = vv.y;
        *(uint32_t*)&Vh[i][d + 4] = vv.z; *(uint32_t*)&Vh[i][d + 6] = vv.w;
    }
    __syncthreads();

    // QK^T, 4x4 per thread; half2 loads over d-pairs, fp32 accumulate
    {
        int ti = (tid >> 4) * 4, tx = tid & 15;
        float s[4][4];
#pragma unroll
        for (int r = 0; r < 4; ++r)
#pragma unroll
            for (int c2 = 0; c2 < 4; ++c2) s[r][c2] = 0.f;
        int ty = tid >> 4;
#pragma unroll
        for (int d2 = 0; d2 < 16; ++d2) {
            float2 q2[4], k2[4];
#pragma unroll
            for (int r = 0; r < 4; ++r)
                q2[r] = __half22float2(*(const __half2*)&Qh[ty * 4 + r][2 * d2]);
#pragma unroll
            for (int c2 = 0; c2 < 4; ++c2)
                k2[c2] = __half22float2(*(const __half2*)&Kh[tx + 16 * c2][2 * d2]);
#pragma unroll
            for (int r = 0; r < 4; ++r)
#pragma unroll
                for (int c2 = 0; c2 < 4; ++c2)
                    s[r][c2] += q2[r].x * k2[c2].x + q2[r].y * k2[c2].y;
        }
        const float scale = 0.17677669529663687f;  // 1/sqrt(32)
#pragma unroll
        for (int r = 0; r < 4; ++r)
#pragma unroll
            for (int c2 = 0; c2 < 4; ++c2) S[ty * 4 + r][tx + 16 * c2] = s[r][c2] * scale;
    }
    __syncthreads();

    // softmax: 4 lanes per row, 16 cols each; probs written fp16 to Sh
    {
        int row = tid >> 2, j0 = (tid & 3) * 16;
        float m = -1e30f;
#pragma unroll
        for (int k = 0; k < 16; ++k) m = fmaxf(m, S[row][j0 + k]);
        m = fmaxf(m, __shfl_xor_sync(0xffffffffu, m, 1));
        m = fmaxf(m, __shfl_xor_sync(0xffffffffu, m, 2));
        float sum = 0.f;
#pragma unroll
        for (int k = 0; k < 16; ++k) {
            float e = __expf(S[row][j0 + k] - m);
            Sh[row][j0 + k] = __float2half(e);
            sum += e;
        }
        sum += __shfl_xor_sync(0xffffffffu, sum, 1);
        sum += __shfl_xor_sync(0xffffffffu, sum, 2);
        if ((tid & 3) == 0) rinv[row] = 1.f / sum;
    }
    __syncthreads();

    // SV: rows {g, g+32} x 4 cols per thread; fp16 S and V, fp32 accumulate
    {
        int g = tid >> 3, dc = (tid & 7) * 4;
        float a0[4] = {0.f, 0.f, 0.f, 0.f}, a1[4] = {0.f, 0.f, 0.f, 0.f};
#pragma unroll
        for (int j2 = 0; j2 < 32; ++j2) {
            float2 s0 = __half22float2(*(const __half2*)&Sh[g][2 * j2]);
            float2 s1 = __half22float2(*(const __half2*)&Sh[g + 32][2 * j2]);
            uint2 va = *(const uint2*)&Vh[2 * j2][dc];
            uint2 vb = *(const uint2*)&Vh[2 * j2 + 1][dc];
            float2 va01 = __half22float2(((const __half2*)&va)[0]);
            float2 va23 = __half22float2(((const __half2*)&va)[1]);
            float2 vb01 = __half22float2(((const __half2*)&vb)[0]);
            float2 vb23 = __half22float2(((const __half2*)&vb)[1]);
            a0[0] += s0.x * va01.x + s0.y * vb01.x;
            a0[1] += s0.x * va01.y + s0.y * vb01.y;
            a0[2] += s0.x * va23.x + s0.y * vb23.x;
            a0[3] += s0.x * va23.y + s0.y * vb23.y;
            a1[0] += s1.x * va01.x + s1.y * vb01.x;
            a1[1] += s1.x * va01.y + s1.y * vb01.y;
            a1[2] += s1.x * va23.x + s1.y * vb23.x;
            a1[3] += s1.x * va23.y + s1.y * vb23.y;
        }
        float ri0 = rinv[g], ri1 = rinv[g + 32];
        size_t o0 = (size_t)(win * 64 + g) * 256 + head * 32 + dc;
        size_t o1 = o0 + (size_t)32 * 256;
#pragma unroll
        for (int c2 = 0; c2 < 4; ++c2) {
            oh[o0 + c2] = __float2half(a0[c2] * ri0);
            oh[o1 + c2] = __float2half(a1[c2] * ri1);
        }
    }
}

// ---------------- window reverse + residual + LN2 (fp16 attn2 in) -----------
__global__ __launch_bounds__(256)
void resid_ln2(const float* __restrict__ x, const __half* __restrict__ a,
               const float* __restrict__ g, const float* __restrict__ bb,
               __half* __restrict__ zout) {
    extern __shared__ float xs[];  // [256][65]
    int b = blockIdx.x >> 6, h = blockIdx.x & 63;
    int tid = threadIdx.x;
    const float* xp = x + (size_t)b * 1048576 + h * 64;
#pragma unroll
    for (int it = 0; it < 64; ++it) {
        int e = it * 256 + tid;
        int c = e >> 6, w = e & 63;
        xs[c * 65 + w] = xp[(size_t)c * 4096 + w];
    }
    __syncthreads();
    int warp = tid >> 5, lane = tid & 31;
#pragma unroll 1
    for (int t = 0; t < 8; ++t) {
        int w = t * 8 + warp;
        size_t tb = (size_t)src_to_token(b, h, w) * 256;
        float v[8]; float s = 0.f;
#pragma unroll
        for (int k = 0; k < 8; k++) {
            int c = k * 32 + lane;
            v[k] = xs[c * 65 + w] + __half2float(a[tb + c]);
            s += v[k];
        }
#pragma unroll
        for (int o2 = 16; o2; o2 >>= 1) s += __shfl_xor_sync(0xffffffffu, s, o2);
        float mu = s * 0.00390625f;
        float q = 0.f;
#pragma unroll
        for (int k = 0; k < 8; k++) { float d = v[k] - mu; q += d * d; }
#pragma unroll
        for (int o2 = 16; o2; o2 >>= 1) q += __shfl_xor_sync(0xffffffffu, q, o2);
        float rs = rsqrtf(q * 0.00390625f + 1e-6f);
#pragma unroll
        for (int k = 0; k < 8; k++) {
            int c = k * 32 + lane;
            zout[tb + c] = __float2half((v[k] - mu) * rs * g[c] + bb[c]);
        }
    }
}

// ---------------- final: out = x + attn2 + mlp (fp16 residual streams) -------
#define FIN_SMEM (64 * 257 * 4)
__global__ __launch_bounds__(256)
void final_add(const float* __restrict__ x, const __half* __restrict__ a,
               const __half* __restrict__ m, float* __restrict__ out) {
    extern __shared__ float ss[];  // [64 tokens][257]
    int b = blockIdx.x >> 6, h = blockIdx.x & 63;
    int tid = threadIdx.x;
    int warp = tid >> 5, lane = tid & 31;
#pragma unroll 1
    for (int t = 0; t < 8; ++t) {
        int w = t * 8 + warp;
        size_t tb = (size_t)src_to_token(b, h, w) * 256;
#pragma unroll
        for (int k = 0; k < 8; k++) {
            int c = k * 32 + lane;
            ss[w * 257 + c] = __half2float(a[tb + c]) + __half2float(m[tb + c]);
        }
    }
    __syncthreads();
    const float* xp = x + (size_t)b * 1048576 + h * 64;
    float* op = out + (size_t)b * 1048576 + h * 64;
#pragma unroll
    for (int it = 0; it < 64; ++it) {
        int e = it * 256 + tid;
        int c = e >> 6, w = e & 63;
        op[(size_t)c * 4096 + w] = xp[(size_t)c * 4096 + w] + ss[w * 257 + c];
    }
}

// ---------------- launch ----------------
extern "C" void kernel_launch(void* const* d_in, const int* in_sizes, int n_in,
                              void* d_out, int out_size) {
    const float* x      = (const float*)d_in[0];
    const float* n1g    = (const float*)d_in[1];
    const float* n1b    = (const float*)d_in[2];
    const float* in_w   = (const float*)d_in[3];
    const float* in_b   = (const float*)d_in[4];
    const float* out_w  = (const float*)d_in[5];
    const float* out_b  = (const float*)d_in[6];
    const float* proj_w = (const float*)d_in[7];
    const float* proj_b = (const float*)d_in[8];
    const float* n2g    = (const float*)d_in[9];
    const float* n2b    = (const float*)d_in[10];
    const float* fc1_w  = (const float*)d_in[11];
    const float* fc1_b  = (const float*)d_in[12];
    const float* fc2_w  = (const float*)d_in[13];
    const float* fc2_b  = (const float*)d_in[14];
    float* out = (float*)d_out;

    __half *xn, *qkv, *at, *attn2, *zb2, *h1, *mlp, *wp;
    float *bcomb;
    cudaGetSymbolAddress((void**)&xn,    g_xn);
    cudaGetSymbolAddress((void**)&qkv,   g_qkv);
    cudaGetSymbolAddress((void**)&at,    g_at);
    cudaGetSymbolAddress((void**)&attn2, g_attn2);
    cudaGetSymbolAddress((void**)&zb2,   g_z);
    cudaGetSymbolAddress((void**)&h1,    g_h1);
    cudaGetSymbolAddress((void**)&mlp,   g_mlp);
    cudaGetSymbolAddress((void**)&wp,    g_w);
    cudaGetSymbolAddress((void**)&bcomb, g_bcomb);

    cudaFuncSetAttribute(mma_gemm<1, false>, cudaFuncAttributeMaxDynamicSharedMemorySize, GEMM_SMEM);
    cudaFuncSetAttribute(mma_gemm<1, true >, cudaFuncAttributeMaxDynamicSharedMemorySize, GEMM_SMEM);
    cudaFuncSetAttribute(ln1_part,  cudaFuncAttributeMaxDynamicSharedMemorySize, LN_SMEM);
    cudaFuncSetAttribute(resid_ln2, cudaFuncAttributeMaxDynamicSharedMemorySize, LN_SMEM);
    cudaFuncSetAttribute(final_add, cudaFuncAttributeMaxDynamicSharedMemorySize, FIN_SMEM);

    // prep: weight conversion (1 launch) + combined out/proj weight
    cvtw3<<<2816, 256>>>(in_w, fc1_w, fc2_w, wp);
    wcomb<<<256, 256>>>(proj_w, out_w, out_b, proj_b, wp, bcomb);

    ln1_part<<<1024, 256, LN_SMEM>>>(x, n1g, n1b, xn);

    // qkv: [65536,768] = xn @ in_w^T  (fp16 out)
    mma_gemm<1, false><<<dim3(6, 512), 256, GEMM_SMEM>>>(
        xn, wp + OFF_INW, in_b, nullptr, qkv, 768, 256);

    attn_kernel<<<dim3(1024, 8), 256>>>(qkv, at);

    // combined out_w∘proj_w: [65536,256]  (fp16 out)
    mma_gemm<1, false><<<dim3(2, 512), 256, GEMM_SMEM>>>(
        at, wp + OFF_CMBW, bcomb, nullptr, attn2, 256, 256);

    resid_ln2<<<1024, 256, LN_SMEM>>>(x, attn2, n2g, n2b, zb2);

    // fc1 + gelu: [65536,1024]  (fp16 out)
    mma_gemm<1, true><<<dim3(8, 512), 256, GEMM_SMEM>>>(
        zb2, wp + OFF_FC1W, fc1_b, nullptr, h1, 1024, 256);

    // fc2: [65536,256], K=1024  (fp16 out)
    mma_gemm<1, false><<<dim3(2, 512), 256, GEMM_SMEM>>>(
        h1, wp + OFF_FC2W, fc2_b, nullptr, mlp, 256, 1024);

    final_add<<<1024, 256, FIN_SMEM>>>(x, attn2, mlp, out);
}